// round 12
// baseline (speedup 1.0000x reference)
#include <cuda_runtime.h>
#include <cuda_fp16.h>
#include <cstdint>

// Dims fixed by setup_inputs: B=256, Q=256, S=512, D=1024
#define NB 256
#define NQ 256
#define NS 512
#define ND 1024
#define EPS 1e-8f
#define SLOPE 0.1f
#define SMOOTH 9.0f

__device__ float g_part[2][NB * NS];  // per-(q-block) partial sum of squares
__device__ float g_invden[NB * NQ];
__device__ __align__(16) __half g_ah[(size_t)NB * NS * NQ];  // fp16 attn (67MB)
__device__ __align__(16) __half g_ch[(size_t)NB * NS * ND];  // fp16 ctx (268MB)

// ---------------------------------------------------------------------------
// helpers
// ---------------------------------------------------------------------------
__device__ __forceinline__ void ldsm4(uint32_t* r, uint32_t addr) {
  asm volatile("ldmatrix.sync.aligned.m8n8.x4.shared.b16 {%0,%1,%2,%3}, [%4];"
               : "=r"(r[0]), "=r"(r[1]), "=r"(r[2]), "=r"(r[3]) : "r"(addr));
}
__device__ __forceinline__ void ldsm4t(uint32_t* r, uint32_t addr) {
  asm volatile("ldmatrix.sync.aligned.m8n8.x4.trans.shared.b16 {%0,%1,%2,%3}, [%4];"
               : "=r"(r[0]), "=r"(r[1]), "=r"(r[2]), "=r"(r[3]) : "r"(addr));
}
__device__ __forceinline__ void mma16816(float* c, const uint32_t* a, const uint32_t* b) {
  asm volatile(
      "mma.sync.aligned.m16n8k16.row.col.f32.f16.f16.f32 "
      "{%0,%1,%2,%3}, {%4,%5,%6,%7}, {%8,%9}, {%0,%1,%2,%3};"
      : "+f"(c[0]), "+f"(c[1]), "+f"(c[2]), "+f"(c[3])
      : "r"(a[0]), "r"(a[1]), "r"(a[2]), "r"(a[3]), "r"(b[0]), "r"(b[1]));
}
__device__ __forceinline__ uint32_t smem_u32(const void* p) {
  uint32_t a;
  asm("{ .reg .u64 t; cvta.to.shared.u64 t, %1; cvt.u32.u64 %0, t; }" : "=r"(a) : "l"(p));
  return a;
}
// fp32x4 -> fp16x4 (RN)
__device__ __forceinline__ uint2 cvt4h(float4 v) {
  __half2 h0 = __floats2half2_rn(v.x, v.y);
  __half2 h1 = __floats2half2_rn(v.z, v.w);
  uint2 h;
  h.x = *(uint32_t*)&h0;
  h.y = *(uint32_t*)&h1;
  return h;
}

// ===========================================================================
// GEMM1: P[s][q] = leakyrelu( sum_d ctx[s][d]*qry[q][d] ), fp16 x fp16 / fp32.
// m=s (A=ctx), n=q (B=qry), k=d. CTA 128x128, K-chunk 32, 8 warps (2m x 4n).
// qblk==0 CTAs additionally export the cvt'd fp16 ctx tiles to g_ch
// (bit-identical to the values GEMM2 would convert itself).
// Epilogue accumulates per-row sum of leaky^2 into g_part (deterministic).
// ===========================================================================
#define P1 40  // smem row stride (half)

__global__ __launch_bounds__(256, 2) void k_scores_mma(
    const float* __restrict__ qry, const float* __restrict__ ctx,
    float* __restrict__ P) {
  __shared__ __align__(16) __half sAh[2][128 * P1];
  __shared__ __align__(16) __half sBh[2][128 * P1];
  __shared__ float sred[4][128];

  const int t = threadIdx.x, w = t >> 5, lane = t & 31;
  const int b = blockIdx.z, qblk = blockIdx.x, q0 = qblk * 128, s0 = blockIdx.y * 128;
  const int warp_m = w >> 2, warp_n = w & 3;

  const int lr = lane >> 3, lc8 = lane & 7;
  const float* Abase = ctx + ((size_t)(b * NS + s0)) * ND;  // rows = s
  const float* Bbase = qry + ((size_t)(b * NQ + q0)) * ND;  // rows = q
  __half* Cex = g_ch + ((size_t)(b * NS + s0)) * ND;        // fp16 ctx export

  // ldmatrix lane addressing (non-trans) — verified mapping
  const int g = lane >> 3, r8 = lane & 7;
  const int a_row = (g & 1) * 8 + r8, a_col = (g >> 1) * 8;
  const int b_row = (g >> 1) * 8 + r8, b_col = (g & 1) * 8;

  float acc[4][4][4];
#pragma unroll
  for (int i = 0; i < 4; i++)
#pragma unroll
    for (int j = 0; j < 4; j++)
#pragma unroll
      for (int k = 0; k < 4; k++) acc[i][j][k] = 0.0f;

  float4 stA[4], stB[4];
  const int col = lc8 * 4;
#pragma unroll
  for (int r4 = 0; r4 < 4; r4++) {
    const int row = r4 * 32 + w * 4 + lr;
    stA[r4] = *(const float4*)(Abase + (size_t)row * ND + col);
    stB[r4] = *(const float4*)(Bbase + (size_t)row * ND + col);
  }

  const int NCH = ND / 32;  // 32 chunks
  for (int c = 0; c < NCH; c++) {
    const int buf = c & 1;
#pragma unroll
    for (int r4 = 0; r4 < 4; r4++) {
      const int row = r4 * 32 + w * 4 + lr;
      uint2 ha = cvt4h(stA[r4]);
      *(uint2*)&sAh[buf][row * P1 + col] = ha;
      *(uint2*)&sBh[buf][row * P1 + col] = cvt4h(stB[r4]);
      if (qblk == 0)  // export fp16 ctx (uniform branch per CTA)
        *(uint2*)(Cex + (size_t)row * ND + c * 32 + col) = ha;
    }
    __syncthreads();  // single sync per chunk (double buffer)

    if (c + 1 < NCH) {  // prefetch next chunk into regs; hidden by mma
      const int kc = (c + 1) * 32;
#pragma unroll
      for (int r4 = 0; r4 < 4; r4++) {
        const int row = r4 * 32 + w * 4 + lr;
        stA[r4] = *(const float4*)(Abase + (size_t)row * ND + kc + col);
        stB[r4] = *(const float4*)(Bbase + (size_t)row * ND + kc + col);
      }
    }

    const uint32_t aH = smem_u32(sAh[buf]);
    const uint32_t bH = smem_u32(sBh[buf]);
#pragma unroll
    for (int kk = 0; kk < 32; kk += 16) {
      uint32_t bq[2][4];
#pragma unroll
      for (int np = 0; np < 2; np++) {
        const uint32_t off = ((warp_n * 32 + np * 16 + b_row) * P1 + kk + b_col) * 2;
        ldsm4(bq[np], bH + off);
      }
#pragma unroll
      for (int mi = 0; mi < 4; mi++) {
        uint32_t ah[4];
        const uint32_t off = ((warp_m * 64 + mi * 16 + a_row) * P1 + kk + a_col) * 2;
        ldsm4(ah, aH + off);
#pragma unroll
        for (int nt = 0; nt < 4; nt++) {
          mma16816(acc[mi][nt], ah, &bq[nt >> 1][(nt & 1) * 2]);
        }
      }
    }
  }

  // epilogue: leaky relu, write P[s][q], accumulate row sums of squares
  const int gm = lane >> 2, tg = lane & 3;
  float* Pb = P + (size_t)b * NS * NQ;
  float rsum[4][2];
#pragma unroll
  for (int mi = 0; mi < 4; mi++) {
    rsum[mi][0] = 0.0f;
    rsum[mi][1] = 0.0f;
    const int sg = s0 + warp_m * 64 + mi * 16 + gm;
#pragma unroll
    for (int nt = 0; nt < 4; nt++) {
      const int qg = q0 + warp_n * 32 + nt * 8 + tg * 2;
      float* c = acc[mi][nt];
      float2 v0 = make_float2(c[0] > 0.f ? c[0] : SLOPE * c[0],
                              c[1] > 0.f ? c[1] : SLOPE * c[1]);
      float2 v1 = make_float2(c[2] > 0.f ? c[2] : SLOPE * c[2],
                              c[3] > 0.f ? c[3] : SLOPE * c[3]);
      *(float2*)(Pb + (size_t)sg * NQ + qg) = v0;
      *(float2*)(Pb + (size_t)(sg + 8) * NQ + qg) = v1;
      rsum[mi][0] += v0.x * v0.x + v0.y * v0.y;
      rsum[mi][1] += v1.x * v1.x + v1.y * v1.y;
    }
  }
#pragma unroll
  for (int mi = 0; mi < 4; mi++) {
#pragma unroll
    for (int h = 0; h < 2; h++) {
      float s = rsum[mi][h];
      s += __shfl_xor_sync(0xffffffffu, s, 1);
      s += __shfl_xor_sync(0xffffffffu, s, 2);
      if (tg == 0) sred[warp_n][warp_m * 64 + mi * 16 + h * 8 + gm] = s;
    }
  }
  __syncthreads();
  if (t < 128) {
    float s = sred[0][t] + sred[1][t] + sred[2][t] + sred[3][t];
    g_part[qblk][(size_t)b * NS + s0 + t] = s;
  }
}

// ===========================================================================
// Fused softmax: per (b, 64-wide q tile), cache exp'd scores in smem.
// Computes invnorm (from g_part), denominators, rescales, writes fp32 attnT
// and fp16 attn (g_ah) for GEMM2. One read + one write pass over P.
// ===========================================================================
#define QT 64
#define TPAD 68  // padded row stride (floats)
#define SM_SOFT ((NS * TPAD + NS + 64 + 4 * 64) * 4)

__global__ __launch_bounds__(256) void k_softmax(float* __restrict__ P) {
  extern __shared__ float sm[];
  float (*tile)[TPAD] = (float(*)[TPAD])sm;
  float* siv = sm + NS * TPAD;     // [512] invnorm
  float* sden = siv + NS;          // [64] invden
  float* spart = sden + 64;        // [4][64] partials

  const int b = blockIdx.y, q0 = blockIdx.x * QT;
  const int t = threadIdx.x;

  for (int s = t; s < NS; s += 256)
    siv[s] = 1.0f / (sqrtf(g_part[0][(size_t)b * NS + s] +
                           g_part[1][(size_t)b * NS + s]) + EPS);
  __syncthreads();

  // pass1: load + exp into smem tile (logits bounded in [-9,9], no max needed)
  float* Pb = P + (size_t)b * NS * NQ;
  for (int idx = t; idx < NS * (QT / 4); idx += 256) {
    const int row = idx >> 4, c4 = (idx & 15) * 4;
    float4 v = *(const float4*)(Pb + (size_t)row * NQ + q0 + c4);
    const float iv = siv[row];
    v.x = __expf(SMOOTH * v.x * iv);
    v.y = __expf(SMOOTH * v.y * iv);
    v.z = __expf(SMOOTH * v.z * iv);
    v.w = __expf(SMOOTH * v.w * iv);
    *(float4*)&tile[row][c4] = v;
  }
  __syncthreads();

  // denominators: 4 partials of 128 s each per q column
  {
    const int q = t & 63, part = t >> 6;
    float s = 0.0f;
    const int r0 = part * 128;
#pragma unroll 4
    for (int r = 0; r < 128; r++) s += tile[r0 + r][q];
    spart[part * 64 + q] = s;
  }
  __syncthreads();
  if (t < 64) {
    const float inv = 1.0f / (spart[t] + spart[64 + t] + spart[128 + t] + spart[192 + t]);
    sden[t] = inv;
    g_invden[b * NQ + q0 + t] = inv;  // (kept for completeness)
  }
  __syncthreads();

  // pass2: scale, write fp32 P and fp16 g_ah
  __half* Ab = g_ah + (size_t)b * NS * NQ;
  for (int idx = t; idx < NS * (QT / 4); idx += 256) {
    const int row = idx >> 4, c4 = (idx & 15) * 4;
    float4 v = *(const float4*)&tile[row][c4];
    v.x *= sden[c4 + 0];
    v.y *= sden[c4 + 1];
    v.z *= sden[c4 + 2];
    v.w *= sden[c4 + 3];
    *(float4*)(Pb + (size_t)row * NQ + q0 + c4) = v;
    *(uint2*)(Ab + (size_t)row * NQ + q0 + c4) = cvt4h(v);
  }
}

// ===========================================================================
// GEMM2: W[q][d] = sum_s attn[s][q]*ctx[s][d], fp16 x fp16 / fp32.
// m=q (A = g_ah fp16, ldsm.trans), n=d (B = g_ch fp16, ldsm.trans), k=s.
// Both operands pre-converted fp16: no in-loop cvt, half the LDG bytes.
// ===========================================================================
#define P2 136  // smem row stride (half)

__global__ __launch_bounds__(256, 2) void k_weighted_mma(float* __restrict__ W) {
  __shared__ __align__(16) __half sAh[2][32 * P2];
  __shared__ __align__(16) __half sBh[2][32 * P2];

  const int t = threadIdx.x, w = t >> 5, lane = t & 31;
  const int b = blockIdx.z, d0 = blockIdx.x * 128, q0 = blockIdx.y * 128;
  const int warp_m = w >> 2, warp_n = w & 3;

  const int lr = lane >> 3, lc8 = lane & 7;
  const __half* Ab = g_ah + (size_t)b * NS * NQ;
  const __half* Bb = g_ch + (size_t)b * NS * ND;

  // ldmatrix.trans lane addressing — verified mapping
  const int g = lane >> 3, r8 = lane & 7;
  const int a_k = (g >> 1) * 8 + r8, a_m = (g & 1) * 8;
  const int b_k = (g & 1) * 8 + r8, b_n = (g >> 1) * 8;

  float acc[4][4][4];
#pragma unroll
  for (int i = 0; i < 4; i++)
#pragma unroll
    for (int j = 0; j < 4; j++)
#pragma unroll
      for (int k = 0; k < 4; k++) acc[i][j][k] = 0.0f;

  uint2 stA[4], stB[4];
  const int row = w * 4 + lr;  // 0..31
#pragma unroll
  for (int cr = 0; cr < 4; cr++) {
    const int col = cr * 32 + lc8 * 4;
    stA[cr] = *(const uint2*)(Ab + (size_t)row * NQ + q0 + col);
    stB[cr] = *(const uint2*)(Bb + (size_t)row * ND + d0 + col);
  }

  const int NCH = NS / 32;  // 16 chunks
  for (int c = 0; c < NCH; c++) {
    const int buf = c & 1;
#pragma unroll
    for (int cr = 0; cr < 4; cr++) {
      const int col = cr * 32 + lc8 * 4;
      *(uint2*)&sAh[buf][row * P2 + col] = stA[cr];
      *(uint2*)&sBh[buf][row * P2 + col] = stB[cr];
    }
    __syncthreads();

    if (c + 1 < NCH) {
      const int sc = (c + 1) * 32;
#pragma unroll
      for (int cr = 0; cr < 4; cr++) {
        const int col = cr * 32 + lc8 * 4;
        stA[cr] = *(const uint2*)(Ab + (size_t)(sc + row) * NQ + q0 + col);
        stB[cr] = *(const uint2*)(Bb + (size_t)(sc + row) * ND + d0 + col);
      }
    }

    const uint32_t aH = smem_u32(sAh[buf]);
    const uint32_t bH = smem_u32(sBh[buf]);
#pragma unroll
    for (int kk = 0; kk < 32; kk += 16) {
      uint32_t bq[2][4];
#pragma unroll
      for (int np = 0; np < 2; np++) {
        const uint32_t off = ((kk + b_k) * P2 + warp_n * 32 + np * 16 + b_n) * 2;
        ldsm4t(bq[np], bH + off);
      }
#pragma unroll
      for (int mi = 0; mi < 4; mi++) {
        uint32_t ah[4];
        const uint32_t off = ((kk + a_k) * P2 + warp_m * 64 + mi * 16 + a_m) * 2;
        ldsm4t(ah, aH + off);
#pragma unroll
        for (int nt = 0; nt < 4; nt++) {
          mma16816(acc[mi][nt], ah, &bq[nt >> 1][(nt & 1) * 2]);
        }
      }
    }
  }

  const int gm = lane >> 2, tg = lane & 3;
  float* Wb = W + (size_t)b * NQ * ND;
#pragma unroll
  for (int mi = 0; mi < 4; mi++) {
    const int qg = q0 + warp_m * 64 + mi * 16 + gm;
#pragma unroll
    for (int nt = 0; nt < 4; nt++) {
      const int dg = d0 + warp_n * 32 + nt * 8 + tg * 2;
      float* c = acc[mi][nt];
      *(float2*)(Wb + (size_t)qg * ND + dg) = make_float2(c[0], c[1]);
      *(float2*)(Wb + (size_t)(qg + 8) * ND + dg) = make_float2(c[2], c[3]);
    }
  }
}

// ---------------------------------------------------------------------------
// d_out = [ weighted (B,Q,D) | attnT (B,S,Q) ]; attnT region doubles as
// scratch for the score matrix through the softmax chain.
// ---------------------------------------------------------------------------
extern "C" void kernel_launch(void* const* d_in, const int* in_sizes, int n_in,
                              void* d_out, int out_size) {
  const float* qry = (const float*)d_in[0];  // (B,Q,D)
  const float* ctx = (const float*)d_in[1];  // (B,S,D)
  float* W = (float*)d_out;                         // (B,Q,D)
  float* P = (float*)d_out + (size_t)NB * NQ * ND;  // (B,S,Q)

  cudaFuncSetAttribute(k_softmax, cudaFuncAttributeMaxDynamicSharedMemorySize, SM_SOFT);

  {
    dim3 g(NQ / 128, NS / 128, NB);  // (2, 4, 256)
    k_scores_mma<<<g, 256>>>(qry, ctx, P);
  }
  {
    dim3 g(NQ / QT, NB);  // (4, 256)
    k_softmax<<<g, 256, SM_SOFT>>>(P);
  }
  {
    dim3 g(ND / 128, NQ / 128, NB);  // (8, 2, 256)
    k_weighted_mma<<<g, 256>>>(W);
  }
}

// round 13
// speedup vs baseline: 1.0677x; 1.0677x over previous
#include <cuda_runtime.h>
#include <cuda_fp16.h>
#include <cstdint>

// Dims fixed by setup_inputs: B=256, Q=256, S=512, D=1024
#define NB 256
#define NQ 256
#define NS 512
#define ND 1024
#define EPS 1e-8f
#define SLOPE 0.1f
#define SMOOTH 9.0f

__device__ float g_part[2][NB * NS];  // per-(q-block) partial sum of squares
__device__ __align__(16) __half g_ah[(size_t)NB * NS * NQ];  // fp16 attn (67MB)

// ---------------------------------------------------------------------------
// helpers
// ---------------------------------------------------------------------------
__device__ __forceinline__ void ldsm4(uint32_t* r, uint32_t addr) {
  asm volatile("ldmatrix.sync.aligned.m8n8.x4.shared.b16 {%0,%1,%2,%3}, [%4];"
               : "=r"(r[0]), "=r"(r[1]), "=r"(r[2]), "=r"(r[3]) : "r"(addr));
}
__device__ __forceinline__ void ldsm4t(uint32_t* r, uint32_t addr) {
  asm volatile("ldmatrix.sync.aligned.m8n8.x4.trans.shared.b16 {%0,%1,%2,%3}, [%4];"
               : "=r"(r[0]), "=r"(r[1]), "=r"(r[2]), "=r"(r[3]) : "r"(addr));
}
__device__ __forceinline__ void mma16816(float* c, const uint32_t* a, const uint32_t* b) {
  asm volatile(
      "mma.sync.aligned.m16n8k16.row.col.f32.f16.f16.f32 "
      "{%0,%1,%2,%3}, {%4,%5,%6,%7}, {%8,%9}, {%0,%1,%2,%3};"
      : "+f"(c[0]), "+f"(c[1]), "+f"(c[2]), "+f"(c[3])
      : "r"(a[0]), "r"(a[1]), "r"(a[2]), "r"(a[3]), "r"(b[0]), "r"(b[1]));
}
__device__ __forceinline__ uint32_t smem_u32(const void* p) {
  uint32_t a;
  asm("{ .reg .u64 t; cvta.to.shared.u64 t, %1; cvt.u32.u64 %0, t; }" : "=r"(a) : "l"(p));
  return a;
}
// fp32x4 -> fp16x4 (RN)
__device__ __forceinline__ uint2 cvt4h(float4 v) {
  __half2 h0 = __floats2half2_rn(v.x, v.y);
  __half2 h1 = __floats2half2_rn(v.z, v.w);
  uint2 h;
  h.x = *(uint32_t*)&h0;
  h.y = *(uint32_t*)&h1;
  return h;
}

// ===========================================================================
// GEMM1 (R11 form): P[s][q] = leakyrelu( sum_d ctx[s][d]*qry[q][d] ).
// fp16 x fp16 / fp32 acc. m=s (A=ctx), n=q (B=qry), k=d. CTA 128x128,
// K-chunk 32, 8 warps (2m x 4n). Double-buffered fp16 smem, one sync/chunk,
// register prefetch. Epilogue: row sums of leaky^2 -> g_part.
// ===========================================================================
#define P1 40  // smem row stride (half)

__global__ __launch_bounds__(256, 2) void k_scores_mma(
    const float* __restrict__ qry, const float* __restrict__ ctx,
    float* __restrict__ P) {
  __shared__ __align__(16) __half sAh[2][128 * P1];
  __shared__ __align__(16) __half sBh[2][128 * P1];
  __shared__ float sred[4][128];

  const int t = threadIdx.x, w = t >> 5, lane = t & 31;
  const int b = blockIdx.z, qblk = blockIdx.x, q0 = qblk * 128, s0 = blockIdx.y * 128;
  const int warp_m = w >> 2, warp_n = w & 3;

  const int lr = lane >> 3, lc8 = lane & 7;
  const float* Abase = ctx + ((size_t)(b * NS + s0)) * ND;  // rows = s
  const float* Bbase = qry + ((size_t)(b * NQ + q0)) * ND;  // rows = q

  // ldmatrix lane addressing (non-trans) — verified mapping
  const int g = lane >> 3, r8 = lane & 7;
  const int a_row = (g & 1) * 8 + r8, a_col = (g >> 1) * 8;
  const int b_row = (g >> 1) * 8 + r8, b_col = (g & 1) * 8;

  float acc[4][4][4];
#pragma unroll
  for (int i = 0; i < 4; i++)
#pragma unroll
    for (int j = 0; j < 4; j++)
#pragma unroll
      for (int k = 0; k < 4; k++) acc[i][j][k] = 0.0f;

  float4 stA[4], stB[4];
  const int col = lc8 * 4;
#pragma unroll
  for (int r4 = 0; r4 < 4; r4++) {
    const int row = r4 * 32 + w * 4 + lr;
    stA[r4] = *(const float4*)(Abase + (size_t)row * ND + col);
    stB[r4] = *(const float4*)(Bbase + (size_t)row * ND + col);
  }

  const int NCH = ND / 32;  // 32 chunks
  for (int c = 0; c < NCH; c++) {
    const int buf = c & 1;
#pragma unroll
    for (int r4 = 0; r4 < 4; r4++) {
      const int row = r4 * 32 + w * 4 + lr;
      *(uint2*)&sAh[buf][row * P1 + col] = cvt4h(stA[r4]);
      *(uint2*)&sBh[buf][row * P1 + col] = cvt4h(stB[r4]);
    }
    __syncthreads();  // single sync per chunk (double buffer)

    if (c + 1 < NCH) {  // prefetch next chunk into regs; hidden by mma
      const int kc = (c + 1) * 32;
#pragma unroll
      for (int r4 = 0; r4 < 4; r4++) {
        const int row = r4 * 32 + w * 4 + lr;
        stA[r4] = *(const float4*)(Abase + (size_t)row * ND + kc + col);
        stB[r4] = *(const float4*)(Bbase + (size_t)row * ND + kc + col);
      }
    }

    const uint32_t aH = smem_u32(sAh[buf]);
    const uint32_t bH = smem_u32(sBh[buf]);
#pragma unroll
    for (int kk = 0; kk < 32; kk += 16) {
      uint32_t bq[2][4];
#pragma unroll
      for (int np = 0; np < 2; np++) {
        const uint32_t off = ((warp_n * 32 + np * 16 + b_row) * P1 + kk + b_col) * 2;
        ldsm4(bq[np], bH + off);
      }
#pragma unroll
      for (int mi = 0; mi < 4; mi++) {
        uint32_t ah[4];
        const uint32_t off = ((warp_m * 64 + mi * 16 + a_row) * P1 + kk + a_col) * 2;
        ldsm4(ah, aH + off);
#pragma unroll
        for (int nt = 0; nt < 4; nt++) {
          mma16816(acc[mi][nt], ah, &bq[nt >> 1][(nt & 1) * 2]);
        }
      }
    }
  }

  // epilogue: leaky relu, write P[s][q], accumulate row sums of squares
  const int gm = lane >> 2, tg = lane & 3;
  float* Pb = P + (size_t)b * NS * NQ;
  float rsum[4][2];
#pragma unroll
  for (int mi = 0; mi < 4; mi++) {
    rsum[mi][0] = 0.0f;
    rsum[mi][1] = 0.0f;
    const int sg = s0 + warp_m * 64 + mi * 16 + gm;
#pragma unroll
    for (int nt = 0; nt < 4; nt++) {
      const int qg = q0 + warp_n * 32 + nt * 8 + tg * 2;
      float* c = acc[mi][nt];
      float2 v0 = make_float2(c[0] > 0.f ? c[0] : SLOPE * c[0],
                              c[1] > 0.f ? c[1] : SLOPE * c[1]);
      float2 v1 = make_float2(c[2] > 0.f ? c[2] : SLOPE * c[2],
                              c[3] > 0.f ? c[3] : SLOPE * c[3]);
      *(float2*)(Pb + (size_t)sg * NQ + qg) = v0;
      *(float2*)(Pb + (size_t)(sg + 8) * NQ + qg) = v1;
      rsum[mi][0] += v0.x * v0.x + v0.y * v0.y;
      rsum[mi][1] += v1.x * v1.x + v1.y * v1.y;
    }
  }
#pragma unroll
  for (int mi = 0; mi < 4; mi++) {
#pragma unroll
    for (int h = 0; h < 2; h++) {
      float s = rsum[mi][h];
      s += __shfl_xor_sync(0xffffffffu, s, 1);
      s += __shfl_xor_sync(0xffffffffu, s, 2);
      if (tg == 0) sred[warp_n][warp_m * 64 + mi * 16 + h * 8 + gm] = s;
    }
  }
  __syncthreads();
  if (t < 128) {
    float s = sred[0][t] + sred[1][t] + sred[2][t] + sred[3][t];
    g_part[qblk][(size_t)b * NS + s0 + t] = s;
  }
}

// ===========================================================================
// Fused softmax, occupancy-safe: QT=32 q-tile -> ~77KB smem -> 2 CTAs/SM.
// Per (b, 32-wide q tile): invnorm from g_part, exp into smem, column sums,
// rescale, write fp32 attnT (in place) + fp16 attn (g_ah).
// ===========================================================================
#define QT 32
#define TPAD 36  // padded row stride (floats)
#define SM_SOFT ((NS * TPAD + NS + QT + 8 * QT) * 4)

__global__ __launch_bounds__(256) void k_softmax(float* __restrict__ P) {
  extern __shared__ float sm[];
  float (*tile)[TPAD] = (float(*)[TPAD])sm;
  float* siv = sm + NS * TPAD;      // [512] invnorm
  float* sden = siv + NS;           // [32] invden
  float* spart = sden + QT;         // [8][32] partials

  const int b = blockIdx.y, q0 = blockIdx.x * QT;
  const int t = threadIdx.x;

  for (int s = t; s < NS; s += 256)
    siv[s] = 1.0f / (sqrtf(g_part[0][(size_t)b * NS + s] +
                           g_part[1][(size_t)b * NS + s]) + EPS);
  __syncthreads();

  // pass1: load + exp into smem (logits in [-9,9] after l2norm: no max pass)
  float* Pb = P + (size_t)b * NS * NQ;
  for (int idx = t; idx < NS * (QT / 4); idx += 256) {
    const int row = idx >> 3, c4 = (idx & 7) * 4;
    float4 v = *(const float4*)(Pb + (size_t)row * NQ + q0 + c4);
    const float iv = siv[row];
    v.x = __expf(SMOOTH * v.x * iv);
    v.y = __expf(SMOOTH * v.y * iv);
    v.z = __expf(SMOOTH * v.z * iv);
    v.w = __expf(SMOOTH * v.w * iv);
    *(float4*)&tile[row][c4] = v;
  }
  __syncthreads();

  // column sums: 8 partials of 64 rows each per q column (deterministic)
  {
    const int q = t & 31, part = t >> 5;
    const int r0 = part * 64;
    float s = 0.0f;
#pragma unroll 4
    for (int r = 0; r < 64; r++) s += tile[r0 + r][q];
    spart[part * QT + q] = s;
  }
  __syncthreads();
  if (t < QT) {
    float s = 0.0f;
#pragma unroll
    for (int p = 0; p < 8; p++) s += spart[p * QT + t];
    sden[t] = 1.0f / s;
  }
  __syncthreads();

  // pass2: scale, write fp32 P (attnT) and fp16 g_ah
  __half* Ab = g_ah + (size_t)b * NS * NQ;
  for (int idx = t; idx < NS * (QT / 4); idx += 256) {
    const int row = idx >> 3, c4 = (idx & 7) * 4;
    float4 v = *(const float4*)&tile[row][c4];
    v.x *= sden[c4 + 0];
    v.y *= sden[c4 + 1];
    v.z *= sden[c4 + 2];
    v.w *= sden[c4 + 3];
    *(float4*)(Pb + (size_t)row * NQ + q0 + c4) = v;
    *(uint2*)(Ab + (size_t)row * NQ + q0 + c4) = cvt4h(v);
  }
}

// ===========================================================================
// GEMM2 (R11 form): W[q][d] = sum_s attn[s][q]*ctx[s][d].
// m=q (A = g_ah fp16, ldsm.trans), n=d (B = ctx fp32 -> cvt, ldsm.trans).
// Double-buffered, one sync/chunk, register prefetch.
// ===========================================================================
#define P2 136  // smem row stride (half)

__global__ __launch_bounds__(256, 2) void k_weighted_mma(
    const float* __restrict__ ctx, float* __restrict__ W) {
  __shared__ __align__(16) __half sAh[2][32 * P2];
  __shared__ __align__(16) __half sBh[2][32 * P2];

  const int t = threadIdx.x, w = t >> 5, lane = t & 31;
  const int b = blockIdx.z, d0 = blockIdx.x * 128, q0 = blockIdx.y * 128;
  const int warp_m = w >> 2, warp_n = w & 3;

  const int lr = lane >> 3, lc8 = lane & 7;
  const __half* Ab = g_ah + (size_t)b * NS * NQ;
  const float* Bb = ctx + (size_t)b * NS * ND;

  // ldmatrix.trans lane addressing — verified mapping
  const int g = lane >> 3, r8 = lane & 7;
  const int a_k = (g >> 1) * 8 + r8, a_m = (g & 1) * 8;
  const int b_k = (g & 1) * 8 + r8, b_n = (g >> 1) * 8;

  float acc[4][4][4];
#pragma unroll
  for (int i = 0; i < 4; i++)
#pragma unroll
    for (int j = 0; j < 4; j++)
#pragma unroll
      for (int k = 0; k < 4; k++) acc[i][j][k] = 0.0f;

  uint2 stA[4];
  float4 stB[4];
  const int row = w * 4 + lr;  // 0..31
#pragma unroll
  for (int cr = 0; cr < 4; cr++) {
    const int col = cr * 32 + lc8 * 4;
    stA[cr] = *(const uint2*)(Ab + (size_t)row * NQ + q0 + col);
    stB[cr] = *(const float4*)(Bb + (size_t)row * ND + d0 + col);
  }

  const int NCH = NS / 32;  // 16 chunks
  for (int c = 0; c < NCH; c++) {
    const int buf = c & 1;
#pragma unroll
    for (int cr = 0; cr < 4; cr++) {
      const int col = cr * 32 + lc8 * 4;
      *(uint2*)&sAh[buf][row * P2 + col] = stA[cr];
      *(uint2*)&sBh[buf][row * P2 + col] = cvt4h(stB[cr]);
    }
    __syncthreads();

    if (c + 1 < NCH) {
      const int sc = (c + 1) * 32;
#pragma unroll
      for (int cr = 0; cr < 4; cr++) {
        const int col = cr * 32 + lc8 * 4;
        stA[cr] = *(const uint2*)(Ab + (size_t)(sc + row) * NQ + q0 + col);
        stB[cr] = *(const float4*)(Bb + (size_t)(sc + row) * ND + d0 + col);
      }
    }

    const uint32_t aH = smem_u32(sAh[buf]);
    const uint32_t bH = smem_u32(sBh[buf]);
#pragma unroll
    for (int kk = 0; kk < 32; kk += 16) {
      uint32_t bq[2][4];
#pragma unroll
      for (int np = 0; np < 2; np++) {
        const uint32_t off = ((kk + b_k) * P2 + warp_n * 32 + np * 16 + b_n) * 2;
        ldsm4t(bq[np], bH + off);
      }
#pragma unroll
      for (int mi = 0; mi < 4; mi++) {
        uint32_t ah[4];
        const uint32_t off = ((kk + a_k) * P2 + warp_m * 64 + mi * 16 + a_m) * 2;
        ldsm4t(ah, aH + off);
#pragma unroll
        for (int nt = 0; nt < 4; nt++) {
          mma16816(acc[mi][nt], ah, &bq[nt >> 1][(nt & 1) * 2]);
        }
      }
    }
  }

  const int gm = lane >> 2, tg = lane & 3;
  float* Wb = W + (size_t)b * NQ * ND;
#pragma unroll
  for (int mi = 0; mi < 4; mi++) {
    const int qg = q0 + warp_m * 64 + mi * 16 + gm;
#pragma unroll
    for (int nt = 0; nt < 4; nt++) {
      const int dg = d0 + warp_n * 32 + nt * 8 + tg * 2;
      float* c = acc[mi][nt];
      *(float2*)(Wb + (size_t)qg * ND + dg) = make_float2(c[0], c[1]);
      *(float2*)(Wb + (size_t)(qg + 8) * ND + dg) = make_float2(c[2], c[3]);
    }
  }
}

// ---------------------------------------------------------------------------
// d_out = [ weighted (B,Q,D) | attnT (B,S,Q) ]; attnT region doubles as
// scratch for the score matrix through the softmax chain.
// ---------------------------------------------------------------------------
extern "C" void kernel_launch(void* const* d_in, const int* in_sizes, int n_in,
                              void* d_out, int out_size) {
  const float* qry = (const float*)d_in[0];  // (B,Q,D)
  const float* ctx = (const float*)d_in[1];  // (B,S,D)
  float* W = (float*)d_out;                         // (B,Q,D)
  float* P = (float*)d_out + (size_t)NB * NQ * ND;  // (B,S,Q)

  cudaFuncSetAttribute(k_softmax, cudaFuncAttributeMaxDynamicSharedMemorySize, SM_SOFT);

  {
    dim3 g(NQ / 128, NS / 128, NB);  // (2, 4, 256)
    k_scores_mma<<<g, 256>>>(qry, ctx, P);
  }
  {
    dim3 g(NQ / QT, NB);  // (8, 256)
    k_softmax<<<g, 256, SM_SOFT>>>(P);
  }
  {
    dim3 g(ND / 128, NQ / 128, NB);  // (8, 2, 256)
    k_weighted_mma<<<g, 256>>>(ctx, W);
  }
}

// round 14
// speedup vs baseline: 1.0748x; 1.0067x over previous
#include <cuda_runtime.h>
#include <cuda_fp16.h>
#include <cstdint>

// Dims fixed by setup_inputs: B=256, Q=256, S=512, D=1024
#define NB 256
#define NQ 256
#define NS 512
#define ND 1024
#define EPS 1e-8f
#define SLOPE 0.1f
#define SMOOTH 9.0f
#define LOG2E 1.4426950408889634f

__device__ float g_part[2][NB * NS];  // per-(q-block) partial sum of squares
__device__ __align__(16) __half g_ah[(size_t)NB * NS * NQ];  // fp16 attn (67MB)

// ---------------------------------------------------------------------------
// helpers
// ---------------------------------------------------------------------------
__device__ __forceinline__ void ldsm4(uint32_t* r, uint32_t addr) {
  asm volatile("ldmatrix.sync.aligned.m8n8.x4.shared.b16 {%0,%1,%2,%3}, [%4];"
               : "=r"(r[0]), "=r"(r[1]), "=r"(r[2]), "=r"(r[3]) : "r"(addr));
}
__device__ __forceinline__ void ldsm4t(uint32_t* r, uint32_t addr) {
  asm volatile("ldmatrix.sync.aligned.m8n8.x4.trans.shared.b16 {%0,%1,%2,%3}, [%4];"
               : "=r"(r[0]), "=r"(r[1]), "=r"(r[2]), "=r"(r[3]) : "r"(addr));
}
__device__ __forceinline__ void mma16816(float* c, const uint32_t* a, const uint32_t* b) {
  asm volatile(
      "mma.sync.aligned.m16n8k16.row.col.f32.f16.f16.f32 "
      "{%0,%1,%2,%3}, {%4,%5,%6,%7}, {%8,%9}, {%0,%1,%2,%3};"
      : "+f"(c[0]), "+f"(c[1]), "+f"(c[2]), "+f"(c[3])
      : "r"(a[0]), "r"(a[1]), "r"(a[2]), "r"(a[3]), "r"(b[0]), "r"(b[1]));
}
__device__ __forceinline__ uint32_t smem_u32(const void* p) {
  uint32_t a;
  asm("{ .reg .u64 t; cvta.to.shared.u64 t, %1; cvt.u32.u64 %0, t; }" : "=r"(a) : "l"(p));
  return a;
}
// fp32x4 -> fp16x4 (RN)
__device__ __forceinline__ uint2 cvt4h(float4 v) {
  __half2 h0 = __floats2half2_rn(v.x, v.y);
  __half2 h1 = __floats2half2_rn(v.z, v.w);
  uint2 h;
  h.x = *(uint32_t*)&h0;
  h.y = *(uint32_t*)&h1;
  return h;
}
// FMA-pipe exp: 2^y, y = x*fr already in log2 domain, |y| <= ~13.
__device__ __forceinline__ float exp2_fma(float y) {
  float n = rintf(y);
  float f = y - n;  // [-0.5, 0.5]
  // 2^f degree-5 Taylor in ln2 (rel err ~2.4e-6)
  float p = 1.33335581e-3f;
  p = fmaf(p, f, 9.61812910e-3f);
  p = fmaf(p, f, 5.55041087e-2f);
  p = fmaf(p, f, 2.40226507e-1f);
  p = fmaf(p, f, 6.93147181e-1f);
  p = fmaf(p, f, 1.0f);
  return __int_as_float(__float_as_int(p) + (((int)n) << 23));
}

// ===========================================================================
// GEMM1 (R11/R13 form, unchanged): P[s][q] = leakyrelu(sum_d ctx[s][d]*qry[q][d])
// ===========================================================================
#define P1 40  // smem row stride (half)

__global__ __launch_bounds__(256, 2) void k_scores_mma(
    const float* __restrict__ qry, const float* __restrict__ ctx,
    float* __restrict__ P) {
  __shared__ __align__(16) __half sAh[2][128 * P1];
  __shared__ __align__(16) __half sBh[2][128 * P1];
  __shared__ float sred[4][128];

  const int t = threadIdx.x, w = t >> 5, lane = t & 31;
  const int b = blockIdx.z, qblk = blockIdx.x, q0 = qblk * 128, s0 = blockIdx.y * 128;
  const int warp_m = w >> 2, warp_n = w & 3;

  const int lr = lane >> 3, lc8 = lane & 7;
  const float* Abase = ctx + ((size_t)(b * NS + s0)) * ND;
  const float* Bbase = qry + ((size_t)(b * NQ + q0)) * ND;

  const int g = lane >> 3, r8 = lane & 7;
  const int a_row = (g & 1) * 8 + r8, a_col = (g >> 1) * 8;
  const int b_row = (g >> 1) * 8 + r8, b_col = (g & 1) * 8;

  float acc[4][4][4];
#pragma unroll
  for (int i = 0; i < 4; i++)
#pragma unroll
    for (int j = 0; j < 4; j++)
#pragma unroll
      for (int k = 0; k < 4; k++) acc[i][j][k] = 0.0f;

  float4 stA[4], stB[4];
  const int col = lc8 * 4;
#pragma unroll
  for (int r4 = 0; r4 < 4; r4++) {
    const int row = r4 * 32 + w * 4 + lr;
    stA[r4] = *(const float4*)(Abase + (size_t)row * ND + col);
    stB[r4] = *(const float4*)(Bbase + (size_t)row * ND + col);
  }

  const int NCH = ND / 32;
  for (int c = 0; c < NCH; c++) {
    const int buf = c & 1;
#pragma unroll
    for (int r4 = 0; r4 < 4; r4++) {
      const int row = r4 * 32 + w * 4 + lr;
      *(uint2*)&sAh[buf][row * P1 + col] = cvt4h(stA[r4]);
      *(uint2*)&sBh[buf][row * P1 + col] = cvt4h(stB[r4]);
    }
    __syncthreads();

    if (c + 1 < NCH) {
      const int kc = (c + 1) * 32;
#pragma unroll
      for (int r4 = 0; r4 < 4; r4++) {
        const int row = r4 * 32 + w * 4 + lr;
        stA[r4] = *(const float4*)(Abase + (size_t)row * ND + kc + col);
        stB[r4] = *(const float4*)(Bbase + (size_t)row * ND + kc + col);
      }
    }

    const uint32_t aH = smem_u32(sAh[buf]);
    const uint32_t bH = smem_u32(sBh[buf]);
#pragma unroll
    for (int kk = 0; kk < 32; kk += 16) {
      uint32_t bq[2][4];
#pragma unroll
      for (int np = 0; np < 2; np++) {
        const uint32_t off = ((warp_n * 32 + np * 16 + b_row) * P1 + kk + b_col) * 2;
        ldsm4(bq[np], bH + off);
      }
#pragma unroll
      for (int mi = 0; mi < 4; mi++) {
        uint32_t ah[4];
        const uint32_t off = ((warp_m * 64 + mi * 16 + a_row) * P1 + kk + a_col) * 2;
        ldsm4(ah, aH + off);
#pragma unroll
        for (int nt = 0; nt < 4; nt++) {
          mma16816(acc[mi][nt], ah, &bq[nt >> 1][(nt & 1) * 2]);
        }
      }
    }
  }

  const int gm = lane >> 2, tg = lane & 3;
  float* Pb = P + (size_t)b * NS * NQ;
  float rsum[4][2];
#pragma unroll
  for (int mi = 0; mi < 4; mi++) {
    rsum[mi][0] = 0.0f;
    rsum[mi][1] = 0.0f;
    const int sg = s0 + warp_m * 64 + mi * 16 + gm;
#pragma unroll
    for (int nt = 0; nt < 4; nt++) {
      const int qg = q0 + warp_n * 32 + nt * 8 + tg * 2;
      float* c = acc[mi][nt];
      float2 v0 = make_float2(c[0] > 0.f ? c[0] : SLOPE * c[0],
                              c[1] > 0.f ? c[1] : SLOPE * c[1]);
      float2 v1 = make_float2(c[2] > 0.f ? c[2] : SLOPE * c[2],
                              c[3] > 0.f ? c[3] : SLOPE * c[3]);
      *(float2*)(Pb + (size_t)sg * NQ + qg) = v0;
      *(float2*)(Pb + (size_t)(sg + 8) * NQ + qg) = v1;
      rsum[mi][0] += v0.x * v0.x + v0.y * v0.y;
      rsum[mi][1] += v1.x * v1.x + v1.y * v1.y;
    }
  }
#pragma unroll
  for (int mi = 0; mi < 4; mi++) {
#pragma unroll
    for (int h = 0; h < 2; h++) {
      float s = rsum[mi][h];
      s += __shfl_xor_sync(0xffffffffu, s, 1);
      s += __shfl_xor_sync(0xffffffffu, s, 2);
      if (tg == 0) sred[warp_n][warp_m * 64 + mi * 16 + h * 8 + gm] = s;
    }
  }
  __syncthreads();
  if (t < 128) {
    float s = sred[0][t] + sred[1][t] + sred[2][t] + sred[3][t];
    g_part[qblk][(size_t)b * NS + s0 + t] = s;
  }
}

// ===========================================================================
// Fused softmax v2: FMA-pipe exp + register column partials.
// QT=32 q-tile, ~80KB smem, 2 CTAs/SM. Per (b, q-tile): invnorm from g_part,
// exp (exp2_fma) into smem while accumulating column partials in registers,
// 4KB conflict-free reduce, rescale, write fp32 attnT + fp16 attn.
// ===========================================================================
#define QT 32
#define TPAD 36  // padded row stride (floats)
#define SM_SOFT ((NS * TPAD + NS + QT + 256 * 4) * 4)

__global__ __launch_bounds__(256) void k_softmax(float* __restrict__ P) {
  extern __shared__ float sm[];
  float (*tile)[TPAD] = (float(*)[TPAD])sm;
  float* siv = sm + NS * TPAD;       // [512] SMOOTH*LOG2E/(norm+eps)
  float* sden = siv + NS;            // [32] invden
  float (*spart)[4] = (float(*)[4])(sden + QT);  // [256][4] partials

  const int b = blockIdx.y, q0 = blockIdx.x * QT;
  const int t = threadIdx.x;

  const float KF = SMOOTH * LOG2E;
  for (int s = t; s < NS; s += 256)
    siv[s] = KF / (sqrtf(g_part[0][(size_t)b * NS + s] +
                         g_part[1][(size_t)b * NS + s]) + EPS);
  __syncthreads();

  // pass1: load + exp into smem; accumulate this thread's column partials.
  // thread t covers columns c4..c4+3 (c4 fixed) over rows t>>3 + 32k.
  float* Pb = P + (size_t)b * NS * NQ;
  const int c4 = (t & 7) * 4;
  float4 part = make_float4(0.f, 0.f, 0.f, 0.f);
#pragma unroll
  for (int k = 0; k < 16; k++) {
    const int row = (t >> 3) + 32 * k;
    float4 v = *(const float4*)(Pb + (size_t)row * NQ + q0 + c4);
    const float fr = siv[row];
    v.x = exp2_fma(v.x * fr);
    v.y = exp2_fma(v.y * fr);
    v.z = exp2_fma(v.z * fr);
    v.w = exp2_fma(v.w * fr);
    *(float4*)&tile[row][c4] = v;
    part.x += v.x;
    part.y += v.y;
    part.z += v.z;
    part.w += v.w;
  }
  *(float4*)spart[t] = part;
  __syncthreads();

  // reduce: column c (< 32) = group g=c>>2, comp c&3 over 32 thread-partials.
  // addr pattern spart[g + 8k][comp] -> bank (t + 32k) % 32: conflict-free.
  if (t < QT) {
    const int gidx = t >> 2, comp = t & 3;
    float s = 0.0f;
#pragma unroll
    for (int k = 0; k < 32; k++) s += spart[gidx + 8 * k][comp];
    sden[t] = 1.0f / s;
  }
  __syncthreads();

  // pass2: scale, write fp32 P (attnT) and fp16 g_ah
  __half* Ab = g_ah + (size_t)b * NS * NQ;
  for (int idx = t; idx < NS * (QT / 4); idx += 256) {
    const int row = idx >> 3, cc = (idx & 7) * 4;
    float4 v = *(const float4*)&tile[row][cc];
    v.x *= sden[cc + 0];
    v.y *= sden[cc + 1];
    v.z *= sden[cc + 2];
    v.w *= sden[cc + 3];
    *(float4*)(Pb + (size_t)row * NQ + q0 + cc) = v;
    *(uint2*)(Ab + (size_t)row * NQ + q0 + cc) = cvt4h(v);
  }
}

// ===========================================================================
// GEMM2 (R11/R13 form, unchanged): W[q][d] = sum_s attn[s][q]*ctx[s][d]
// ===========================================================================
#define P2 136  // smem row stride (half)

__global__ __launch_bounds__(256, 2) void k_weighted_mma(
    const float* __restrict__ ctx, float* __restrict__ W) {
  __shared__ __align__(16) __half sAh[2][32 * P2];
  __shared__ __align__(16) __half sBh[2][32 * P2];

  const int t = threadIdx.x, w = t >> 5, lane = t & 31;
  const int b = blockIdx.z, d0 = blockIdx.x * 128, q0 = blockIdx.y * 128;
  const int warp_m = w >> 2, warp_n = w & 3;

  const int lr = lane >> 3, lc8 = lane & 7;
  const __half* Ab = g_ah + (size_t)b * NS * NQ;
  const float* Bb = ctx + (size_t)b * NS * ND;

  const int g = lane >> 3, r8 = lane & 7;
  const int a_k = (g >> 1) * 8 + r8, a_m = (g & 1) * 8;
  const int b_k = (g & 1) * 8 + r8, b_n = (g >> 1) * 8;

  float acc[4][4][4];
#pragma unroll
  for (int i = 0; i < 4; i++)
#pragma unroll
    for (int j = 0; j < 4; j++)
#pragma unroll
      for (int k = 0; k < 4; k++) acc[i][j][k] = 0.0f;

  uint2 stA[4];
  float4 stB[4];
  const int row = w * 4 + lr;
#pragma unroll
  for (int cr = 0; cr < 4; cr++) {
    const int col = cr * 32 + lc8 * 4;
    stA[cr] = *(const uint2*)(Ab + (size_t)row * NQ + q0 + col);
    stB[cr] = *(const float4*)(Bb + (size_t)row * ND + d0 + col);
  }

  const int NCH = NS / 32;
  for (int c = 0; c < NCH; c++) {
    const int buf = c & 1;
#pragma unroll
    for (int cr = 0; cr < 4; cr++) {
      const int col = cr * 32 + lc8 * 4;
      *(uint2*)&sAh[buf][row * P2 + col] = stA[cr];
      *(uint2*)&sBh[buf][row * P2 + col] = cvt4h(stB[cr]);
    }
    __syncthreads();

    if (c + 1 < NCH) {
      const int sc = (c + 1) * 32;
#pragma unroll
      for (int cr = 0; cr < 4; cr++) {
        const int col = cr * 32 + lc8 * 4;
        stA[cr] = *(const uint2*)(Ab + (size_t)(sc + row) * NQ + q0 + col);
        stB[cr] = *(const float4*)(Bb + (size_t)(sc + row) * ND + d0 + col);
      }
    }

    const uint32_t aH = smem_u32(sAh[buf]);
    const uint32_t bH = smem_u32(sBh[buf]);
#pragma unroll
    for (int kk = 0; kk < 32; kk += 16) {
      uint32_t bq[2][4];
#pragma unroll
      for (int np = 0; np < 2; np++) {
        const uint32_t off = ((kk + b_k) * P2 + warp_n * 32 + np * 16 + b_n) * 2;
        ldsm4t(bq[np], bH + off);
      }
#pragma unroll
      for (int mi = 0; mi < 4; mi++) {
        uint32_t ah[4];
        const uint32_t off = ((kk + a_k) * P2 + warp_m * 64 + mi * 16 + a_m) * 2;
        ldsm4t(ah, aH + off);
#pragma unroll
        for (int nt = 0; nt < 4; nt++) {
          mma16816(acc[mi][nt], ah, &bq[nt >> 1][(nt & 1) * 2]);
        }
      }
    }
  }

  const int gm = lane >> 2, tg = lane & 3;
  float* Wb = W + (size_t)b * NQ * ND;
#pragma unroll
  for (int mi = 0; mi < 4; mi++) {
    const int qg = q0 + warp_m * 64 + mi * 16 + gm;
#pragma unroll
    for (int nt = 0; nt < 4; nt++) {
      const int dg = d0 + warp_n * 32 + nt * 8 + tg * 2;
      float* c = acc[mi][nt];
      *(float2*)(Wb + (size_t)qg * ND + dg) = make_float2(c[0], c[1]);
      *(float2*)(Wb + (size_t)(qg + 8) * ND + dg) = make_float2(c[2], c[3]);
    }
  }
}

// ---------------------------------------------------------------------------
// d_out = [ weighted (B,Q,D) | attnT (B,S,Q) ]; attnT region doubles as
// scratch for the score matrix through the softmax chain.
// ---------------------------------------------------------------------------
extern "C" void kernel_launch(void* const* d_in, const int* in_sizes, int n_in,
                              void* d_out, int out_size) {
  const float* qry = (const float*)d_in[0];  // (B,Q,D)
  const float* ctx = (const float*)d_in[1];  // (B,S,D)
  float* W = (float*)d_out;                         // (B,Q,D)
  float* P = (float*)d_out + (size_t)NB * NQ * ND;  // (B,S,Q)

  cudaFuncSetAttribute(k_softmax, cudaFuncAttributeMaxDynamicSharedMemorySize, SM_SOFT);

  {
    dim3 g(NQ / 128, NS / 128, NB);  // (2, 4, 256)
    k_scores_mma<<<g, 256>>>(qry, ctx, P);
  }
  {
    dim3 g(NQ / QT, NB);  // (8, 256)
    k_softmax<<<g, 256, SM_SOFT>>>(P);
  }
  {
    dim3 g(ND / 128, NQ / 128, NB);  // (8, 2, 256)
    k_weighted_mma<<<g, 256>>>(ctx, W);
  }
}

// round 15
// speedup vs baseline: 1.0765x; 1.0015x over previous
#include <cuda_runtime.h>
#include <cuda_fp16.h>
#include <cstdint>

// Dims fixed by setup_inputs: B=256, Q=256, S=512, D=1024
#define NB 256
#define NQ 256
#define NS 512
#define ND 1024
#define EPS 1e-8f
#define SLOPE 0.1f
#define SMOOTH 9.0f
#define LOG2E 1.4426950408889634f

__device__ float g_part[2][NB * NS];  // per-(q-block) partial sum of squares
__device__ __align__(16) __half g_ah[(size_t)NB * NS * NQ];  // fp16 attn (67MB)

// ---------------------------------------------------------------------------
// helpers
// ---------------------------------------------------------------------------
__device__ __forceinline__ void ldsm4(uint32_t* r, uint32_t addr) {
  asm volatile("ldmatrix.sync.aligned.m8n8.x4.shared.b16 {%0,%1,%2,%3}, [%4];"
               : "=r"(r[0]), "=r"(r[1]), "=r"(r[2]), "=r"(r[3]) : "r"(addr));
}
__device__ __forceinline__ void ldsm4t(uint32_t* r, uint32_t addr) {
  asm volatile("ldmatrix.sync.aligned.m8n8.x4.trans.shared.b16 {%0,%1,%2,%3}, [%4];"
               : "=r"(r[0]), "=r"(r[1]), "=r"(r[2]), "=r"(r[3]) : "r"(addr));
}
__device__ __forceinline__ void mma16816(float* c, const uint32_t* a, const uint32_t* b) {
  asm volatile(
      "mma.sync.aligned.m16n8k16.row.col.f32.f16.f16.f32 "
      "{%0,%1,%2,%3}, {%4,%5,%6,%7}, {%8,%9}, {%0,%1,%2,%3};"
      : "+f"(c[0]), "+f"(c[1]), "+f"(c[2]), "+f"(c[3])
      : "r"(a[0]), "r"(a[1]), "r"(a[2]), "r"(a[3]), "r"(b[0]), "r"(b[1]));
}
__device__ __forceinline__ uint32_t smem_u32(const void* p) {
  uint32_t a;
  asm("{ .reg .u64 t; cvta.to.shared.u64 t, %1; cvt.u32.u64 %0, t; }" : "=r"(a) : "l"(p));
  return a;
}
// fp32x4 -> fp16x4 (RN)
__device__ __forceinline__ uint2 cvt4h(float4 v) {
  __half2 h0 = __floats2half2_rn(v.x, v.y);
  __half2 h1 = __floats2half2_rn(v.z, v.w);
  uint2 h;
  h.x = *(uint32_t*)&h0;
  h.y = *(uint32_t*)&h1;
  return h;
}
// FMA-pipe exp: 2^y, y = x*fr already in log2 domain, |y| <= ~13.
__device__ __forceinline__ float exp2_fma(float y) {
  float n = rintf(y);
  float f = y - n;  // [-0.5, 0.5]
  // 2^f degree-5 Taylor in ln2 (rel err ~2.4e-6)
  float p = 1.33335581e-3f;
  p = fmaf(p, f, 9.61812910e-3f);
  p = fmaf(p, f, 5.55041087e-2f);
  p = fmaf(p, f, 2.40226507e-1f);
  p = fmaf(p, f, 6.93147181e-1f);
  p = fmaf(p, f, 1.0f);
  return __int_as_float(__float_as_int(p) + (((int)n) << 23));
}

// ===========================================================================
// GEMM1 (R11/R13 form, unchanged): P[s][q] = leakyrelu(sum_d ctx[s][d]*qry[q][d])
// ===========================================================================
#define P1 40  // smem row stride (half)

__global__ __launch_bounds__(256, 2) void k_scores_mma(
    const float* __restrict__ qry, const float* __restrict__ ctx,
    float* __restrict__ P) {
  __shared__ __align__(16) __half sAh[2][128 * P1];
  __shared__ __align__(16) __half sBh[2][128 * P1];
  __shared__ float sred[4][128];

  const int t = threadIdx.x, w = t >> 5, lane = t & 31;
  const int b = blockIdx.z, qblk = blockIdx.x, q0 = qblk * 128, s0 = blockIdx.y * 128;
  const int warp_m = w >> 2, warp_n = w & 3;

  const int lr = lane >> 3, lc8 = lane & 7;
  const float* Abase = ctx + ((size_t)(b * NS + s0)) * ND;
  const float* Bbase = qry + ((size_t)(b * NQ + q0)) * ND;

  const int g = lane >> 3, r8 = lane & 7;
  const int a_row = (g & 1) * 8 + r8, a_col = (g >> 1) * 8;
  const int b_row = (g >> 1) * 8 + r8, b_col = (g & 1) * 8;

  float acc[4][4][4];
#pragma unroll
  for (int i = 0; i < 4; i++)
#pragma unroll
    for (int j = 0; j < 4; j++)
#pragma unroll
      for (int k = 0; k < 4; k++) acc[i][j][k] = 0.0f;

  float4 stA[4], stB[4];
  const int col = lc8 * 4;
#pragma unroll
  for (int r4 = 0; r4 < 4; r4++) {
    const int row = r4 * 32 + w * 4 + lr;
    stA[r4] = *(const float4*)(Abase + (size_t)row * ND + col);
    stB[r4] = *(const float4*)(Bbase + (size_t)row * ND + col);
  }

  const int NCH = ND / 32;
  for (int c = 0; c < NCH; c++) {
    const int buf = c & 1;
#pragma unroll
    for (int r4 = 0; r4 < 4; r4++) {
      const int row = r4 * 32 + w * 4 + lr;
      *(uint2*)&sAh[buf][row * P1 + col] = cvt4h(stA[r4]);
      *(uint2*)&sBh[buf][row * P1 + col] = cvt4h(stB[r4]);
    }
    __syncthreads();

    if (c + 1 < NCH) {
      const int kc = (c + 1) * 32;
#pragma unroll
      for (int r4 = 0; r4 < 4; r4++) {
        const int row = r4 * 32 + w * 4 + lr;
        stA[r4] = *(const float4*)(Abase + (size_t)row * ND + kc + col);
        stB[r4] = *(const float4*)(Bbase + (size_t)row * ND + kc + col);
      }
    }

    const uint32_t aH = smem_u32(sAh[buf]);
    const uint32_t bH = smem_u32(sBh[buf]);
#pragma unroll
    for (int kk = 0; kk < 32; kk += 16) {
      uint32_t bq[2][4];
#pragma unroll
      for (int np = 0; np < 2; np++) {
        const uint32_t off = ((warp_n * 32 + np * 16 + b_row) * P1 + kk + b_col) * 2;
        ldsm4(bq[np], bH + off);
      }
#pragma unroll
      for (int mi = 0; mi < 4; mi++) {
        uint32_t ah[4];
        const uint32_t off = ((warp_m * 64 + mi * 16 + a_row) * P1 + kk + a_col) * 2;
        ldsm4(ah, aH + off);
#pragma unroll
        for (int nt = 0; nt < 4; nt++) {
          mma16816(acc[mi][nt], ah, &bq[nt >> 1][(nt & 1) * 2]);
        }
      }
    }
  }

  const int gm = lane >> 2, tg = lane & 3;
  float* Pb = P + (size_t)b * NS * NQ;
  float rsum[4][2];
#pragma unroll
  for (int mi = 0; mi < 4; mi++) {
    rsum[mi][0] = 0.0f;
    rsum[mi][1] = 0.0f;
    const int sg = s0 + warp_m * 64 + mi * 16 + gm;
#pragma unroll
    for (int nt = 0; nt < 4; nt++) {
      const int qg = q0 + warp_n * 32 + nt * 8 + tg * 2;
      float* c = acc[mi][nt];
      float2 v0 = make_float2(c[0] > 0.f ? c[0] : SLOPE * c[0],
                              c[1] > 0.f ? c[1] : SLOPE * c[1]);
      float2 v1 = make_float2(c[2] > 0.f ? c[2] : SLOPE * c[2],
                              c[3] > 0.f ? c[3] : SLOPE * c[3]);
      *(float2*)(Pb + (size_t)sg * NQ + qg) = v0;
      *(float2*)(Pb + (size_t)(sg + 8) * NQ + qg) = v1;
      rsum[mi][0] += v0.x * v0.x + v0.y * v0.y;
      rsum[mi][1] += v1.x * v1.x + v1.y * v1.y;
    }
  }
#pragma unroll
  for (int mi = 0; mi < 4; mi++) {
#pragma unroll
    for (int h = 0; h < 2; h++) {
      float s = rsum[mi][h];
      s += __shfl_xor_sync(0xffffffffu, s, 1);
      s += __shfl_xor_sync(0xffffffffu, s, 2);
      if (tg == 0) sred[warp_n][warp_m * 64 + mi * 16 + h * 8 + gm] = s;
    }
  }
  __syncthreads();
  if (t < 128) {
    float s = sred[0][t] + sred[1][t] + sred[2][t] + sred[3][t];
    g_part[qblk][(size_t)b * NS + s0 + t] = s;
  }
}

// ===========================================================================
// Fused softmax v2: FMA-pipe exp + register column partials.
// QT=32 q-tile, ~80KB smem, 2 CTAs/SM. Per (b, q-tile): invnorm from g_part,
// exp (exp2_fma) into smem while accumulating column partials in registers,
// 4KB conflict-free reduce, rescale, write fp32 attnT + fp16 attn.
// ===========================================================================
#define QT 32
#define TPAD 36  // padded row stride (floats)
#define SM_SOFT ((NS * TPAD + NS + QT + 256 * 4) * 4)

__global__ __launch_bounds__(256) void k_softmax(float* __restrict__ P) {
  extern __shared__ float sm[];
  float (*tile)[TPAD] = (float(*)[TPAD])sm;
  float* siv = sm + NS * TPAD;       // [512] SMOOTH*LOG2E/(norm+eps)
  float* sden = siv + NS;            // [32] invden
  float (*spart)[4] = (float(*)[4])(sden + QT);  // [256][4] partials

  const int b = blockIdx.y, q0 = blockIdx.x * QT;
  const int t = threadIdx.x;

  const float KF = SMOOTH * LOG2E;
  for (int s = t; s < NS; s += 256)
    siv[s] = KF / (sqrtf(g_part[0][(size_t)b * NS + s] +
                         g_part[1][(size_t)b * NS + s]) + EPS);
  __syncthreads();

  // pass1: load + exp into smem; accumulate this thread's column partials.
  // thread t covers columns c4..c4+3 (c4 fixed) over rows t>>3 + 32k.
  float* Pb = P + (size_t)b * NS * NQ;
  const int c4 = (t & 7) * 4;
  float4 part = make_float4(0.f, 0.f, 0.f, 0.f);
#pragma unroll
  for (int k = 0; k < 16; k++) {
    const int row = (t >> 3) + 32 * k;
    float4 v = *(const float4*)(Pb + (size_t)row * NQ + q0 + c4);
    const float fr = siv[row];
    v.x = exp2_fma(v.x * fr);
    v.y = exp2_fma(v.y * fr);
    v.z = exp2_fma(v.z * fr);
    v.w = exp2_fma(v.w * fr);
    *(float4*)&tile[row][c4] = v;
    part.x += v.x;
    part.y += v.y;
    part.z += v.z;
    part.w += v.w;
  }
  *(float4*)spart[t] = part;
  __syncthreads();

  // reduce: column c (< 32) = group g=c>>2, comp c&3 over 32 thread-partials.
  // addr pattern spart[g + 8k][comp] -> bank (t + 32k) % 32: conflict-free.
  if (t < QT) {
    const int gidx = t >> 2, comp = t & 3;
    float s = 0.0f;
#pragma unroll
    for (int k = 0; k < 32; k++) s += spart[gidx + 8 * k][comp];
    sden[t] = 1.0f / s;
  }
  __syncthreads();

  // pass2: scale, write fp32 P (attnT) and fp16 g_ah
  __half* Ab = g_ah + (size_t)b * NS * NQ;
  for (int idx = t; idx < NS * (QT / 4); idx += 256) {
    const int row = idx >> 3, cc = (idx & 7) * 4;
    float4 v = *(const float4*)&tile[row][cc];
    v.x *= sden[cc + 0];
    v.y *= sden[cc + 1];
    v.z *= sden[cc + 2];
    v.w *= sden[cc + 3];
    *(float4*)(Pb + (size_t)row * NQ + q0 + cc) = v;
    *(uint2*)(Ab + (size_t)row * NQ + q0 + cc) = cvt4h(v);
  }
}

// ===========================================================================
// GEMM2 (R11/R13 form, unchanged): W[q][d] = sum_s attn[s][q]*ctx[s][d]
// ===========================================================================
#define P2 136  // smem row stride (half)

__global__ __launch_bounds__(256, 2) void k_weighted_mma(
    const float* __restrict__ ctx, float* __restrict__ W) {
  __shared__ __align__(16) __half sAh[2][32 * P2];
  __shared__ __align__(16) __half sBh[2][32 * P2];

  const int t = threadIdx.x, w = t >> 5, lane = t & 31;
  const int b = blockIdx.z, d0 = blockIdx.x * 128, q0 = blockIdx.y * 128;
  const int warp_m = w >> 2, warp_n = w & 3;

  const int lr = lane >> 3, lc8 = lane & 7;
  const __half* Ab = g_ah + (size_t)b * NS * NQ;
  const float* Bb = ctx + (size_t)b * NS * ND;

  const int g = lane >> 3, r8 = lane & 7;
  const int a_k = (g >> 1) * 8 + r8, a_m = (g & 1) * 8;
  const int b_k = (g & 1) * 8 + r8, b_n = (g >> 1) * 8;

  float acc[4][4][4];
#pragma unroll
  for (int i = 0; i < 4; i++)
#pragma unroll
    for (int j = 0; j < 4; j++)
#pragma unroll
      for (int k = 0; k < 4; k++) acc[i][j][k] = 0.0f;

  uint2 stA[4];
  float4 stB[4];
  const int row = w * 4 + lr;
#pragma unroll
  for (int cr = 0; cr < 4; cr++) {
    const int col = cr * 32 + lc8 * 4;
    stA[cr] = *(const uint2*)(Ab + (size_t)row * NQ + q0 + col);
    stB[cr] = *(const float4*)(Bb + (size_t)row * ND + d0 + col);
  }

  const int NCH = NS / 32;
  for (int c = 0; c < NCH; c++) {
    const int buf = c & 1;
#pragma unroll
    for (int cr = 0; cr < 4; cr++) {
      const int col = cr * 32 + lc8 * 4;
      *(uint2*)&sAh[buf][row * P2 + col] = stA[cr];
      *(uint2*)&sBh[buf][row * P2 + col] = cvt4h(stB[cr]);
    }
    __syncthreads();

    if (c + 1 < NCH) {
      const int sc = (c + 1) * 32;
#pragma unroll
      for (int cr = 0; cr < 4; cr++) {
        const int col = cr * 32 + lc8 * 4;
        stA[cr] = *(const uint2*)(Ab + (size_t)(sc + row) * NQ + q0 + col);
        stB[cr] = *(const float4*)(Bb + (size_t)(sc + row) * ND + d0 + col);
      }
    }

    const uint32_t aH = smem_u32(sAh[buf]);
    const uint32_t bH = smem_u32(sBh[buf]);
#pragma unroll
    for (int kk = 0; kk < 32; kk += 16) {
      uint32_t bq[2][4];
#pragma unroll
      for (int np = 0; np < 2; np++) {
        const uint32_t off = ((kk + b_k) * P2 + warp_n * 32 + np * 16 + b_n) * 2;
        ldsm4t(bq[np], bH + off);
      }
#pragma unroll
      for (int mi = 0; mi < 4; mi++) {
        uint32_t ah[4];
        const uint32_t off = ((kk + a_k) * P2 + warp_m * 64 + mi * 16 + a_m) * 2;
        ldsm4t(ah, aH + off);
#pragma unroll
        for (int nt = 0; nt < 4; nt++) {
          mma16816(acc[mi][nt], ah, &bq[nt >> 1][(nt & 1) * 2]);
        }
      }
    }
  }

  const int gm = lane >> 2, tg = lane & 3;
  float* Wb = W + (size_t)b * NQ * ND;
#pragma unroll
  for (int mi = 0; mi < 4; mi++) {
    const int qg = q0 + warp_m * 64 + mi * 16 + gm;
#pragma unroll
    for (int nt = 0; nt < 4; nt++) {
      const int dg = d0 + warp_n * 32 + nt * 8 + tg * 2;
      float* c = acc[mi][nt];
      *(float2*)(Wb + (size_t)qg * ND + dg) = make_float2(c[0], c[1]);
      *(float2*)(Wb + (size_t)(qg + 8) * ND + dg) = make_float2(c[2], c[3]);
    }
  }
}

// ---------------------------------------------------------------------------
// d_out = [ weighted (B,Q,D) | attnT (B,S,Q) ]; attnT region doubles as
// scratch for the score matrix through the softmax chain.
// ---------------------------------------------------------------------------
extern "C" void kernel_launch(void* const* d_in, const int* in_sizes, int n_in,
                              void* d_out, int out_size) {
  const float* qry = (const float*)d_in[0];  // (B,Q,D)
  const float* ctx = (const float*)d_in[1];  // (B,S,D)
  float* W = (float*)d_out;                         // (B,Q,D)
  float* P = (float*)d_out + (size_t)NB * NQ * ND;  // (B,S,Q)

  cudaFuncSetAttribute(k_softmax, cudaFuncAttributeMaxDynamicSharedMemorySize, SM_SOFT);

  {
    dim3 g(NQ / 128, NS / 128, NB);  // (2, 4, 256)
    k_scores_mma<<<g, 256>>>(qry, ctx, P);
  }
  {
    dim3 g(NQ / QT, NB);  // (8, 256)
    k_softmax<<<g, 256, SM_SOFT>>>(P);
  }
  {
    dim3 g(ND / 128, NQ / 128, NB);  // (8, 2, 256)
    k_weighted_mma<<<g, 256>>>(ctx, W);
  }
}

// round 16
// speedup vs baseline: 1.0852x; 1.0081x over previous
#include <cuda_runtime.h>
#include <cuda_fp16.h>
#include <cstdint>

// Dims fixed by setup_inputs: B=256, Q=256, S=512, D=1024
#define NB 256
#define NQ 256
#define NS 512
#define ND 1024
#define EPS 1e-8f
#define SLOPE 0.1f
#define SMOOTH 9.0f
#define LOG2E 1.4426950408889634f

__device__ float g_invnorm[NB * NS];
__device__ __align__(16) __half g_ah[(size_t)NB * NS * NQ];  // fp16 attn (67MB)

// ---------------------------------------------------------------------------
// helpers
// ---------------------------------------------------------------------------
__device__ __forceinline__ void ldsm4(uint32_t* r, uint32_t addr) {
  asm volatile("ldmatrix.sync.aligned.m8n8.x4.shared.b16 {%0,%1,%2,%3}, [%4];"
               : "=r"(r[0]), "=r"(r[1]), "=r"(r[2]), "=r"(r[3]) : "r"(addr));
}
__device__ __forceinline__ void ldsm4t(uint32_t* r, uint32_t addr) {
  asm volatile("ldmatrix.sync.aligned.m8n8.x4.trans.shared.b16 {%0,%1,%2,%3}, [%4];"
               : "=r"(r[0]), "=r"(r[1]), "=r"(r[2]), "=r"(r[3]) : "r"(addr));
}
__device__ __forceinline__ void mma16816(float* c, const uint32_t* a, const uint32_t* b) {
  asm volatile(
      "mma.sync.aligned.m16n8k16.row.col.f32.f16.f16.f32 "
      "{%0,%1,%2,%3}, {%4,%5,%6,%7}, {%8,%9}, {%0,%1,%2,%3};"
      : "+f"(c[0]), "+f"(c[1]), "+f"(c[2]), "+f"(c[3])
      : "r"(a[0]), "r"(a[1]), "r"(a[2]), "r"(a[3]), "r"(b[0]), "r"(b[1]));
}
__device__ __forceinline__ uint32_t smem_u32(const void* p) {
  uint32_t a;
  asm("{ .reg .u64 t; cvta.to.shared.u64 t, %1; cvt.u32.u64 %0, t; }" : "=r"(a) : "l"(p));
  return a;
}
// fp32x4 -> fp16x4 (RN)
__device__ __forceinline__ uint2 cvt4h(float4 v) {
  __half2 h0 = __floats2half2_rn(v.x, v.y);
  __half2 h1 = __floats2half2_rn(v.z, v.w);
  uint2 h;
  h.x = *(uint32_t*)&h0;
  h.y = *(uint32_t*)&h1;
  return h;
}
// FMA-pipe exp2 (|y| <= ~13): rel err ~2.4e-6
__device__ __forceinline__ float exp2_fma(float y) {
  float n = rintf(y);
  float f = y - n;
  float p = 1.33335581e-3f;
  p = fmaf(p, f, 9.61812910e-3f);
  p = fmaf(p, f, 5.55041087e-2f);
  p = fmaf(p, f, 2.40226507e-1f);
  p = fmaf(p, f, 6.93147181e-1f);
  p = fmaf(p, f, 1.0f);
  return __int_as_float(__float_as_int(p) + (((int)n) << 23));
}

// ===========================================================================
// GEMM1: P[s][q] = leakyrelu( sum_d ctx[s][d]*qry[q][d] ), fp16/fp32 acc.
// CTA tile 128(s) x 256(q) — full q range. 8 warps (2m x 4n), warp tile 64x64.
// K-chunk 32, double-buffered fp16 smem, reg prefetch, 1 sync/chunk.
// Epilogue: leaky, P store, COMPLETE row l2-norm -> g_invnorm (no combine).
// ===========================================================================
#define P1 40  // smem row stride (half)
#define G1_ABUF (128 * P1 * 2)   // 10240 B
#define G1_BBUF (256 * P1 * 2)   // 20480 B
#define G1_OFFA 0
#define G1_OFFB (2 * G1_ABUF)    // 20480
#define G1_SMEM (G1_OFFB + 2 * G1_BBUF)  // 61440

__global__ __launch_bounds__(256, 1) void k_scores_mma(
    const float* __restrict__ qry, const float* __restrict__ ctx,
    float* __restrict__ P) {
  extern __shared__ __align__(16) char smg[];
  __shared__ float sred[4][128];
  const uint32_t sb = smem_u32(smg);
  __half* smA = (__half*)(smg + G1_OFFA);
  __half* smB = (__half*)(smg + G1_OFFB);

  const int t = threadIdx.x, w = t >> 5, lane = t & 31;
  const int b = blockIdx.z, s0 = blockIdx.x * 128;
  const int warp_m = w >> 2, warp_n = w & 3;

  const float* Abase = ctx + ((size_t)(b * NS + s0)) * ND;  // 128 s-rows
  const float* Bbase = qry + ((size_t)b * NQ) * ND;         // all 256 q-rows

  // ldmatrix lane addressing (non-trans) — verified mapping
  const int g = lane >> 3, r8 = lane & 7;
  const int a_row = (g & 1) * 8 + r8, a_col = (g >> 1) * 8;
  const int b_row = (g >> 1) * 8 + r8, b_col = (g & 1) * 8;

  float acc[4][8][4];
#pragma unroll
  for (int i = 0; i < 4; i++)
#pragma unroll
    for (int j = 0; j < 8; j++)
#pragma unroll
      for (int k = 0; k < 4; k++) acc[i][j][k] = 0.0f;

  // staging: A 4 float4 (rows t>>3 + 32i), B 8 float4 (rows t>>3 + 32i)
  const int srow = t >> 3, scol = (t & 7) * 4;
  float4 stA[4], stB[8];
#pragma unroll
  for (int i = 0; i < 4; i++)
    stA[i] = *(const float4*)(Abase + (size_t)(srow + 32 * i) * ND + scol);
#pragma unroll
  for (int i = 0; i < 8; i++)
    stB[i] = *(const float4*)(Bbase + (size_t)(srow + 32 * i) * ND + scol);

  const int NCH = ND / 32;  // 32 chunks
  for (int c = 0; c < NCH; c++) {
    const int buf = c & 1;
    __half* A = smA + buf * (128 * P1);
    __half* Bm = smB + buf * (256 * P1);
#pragma unroll
    for (int i = 0; i < 4; i++)
      *(uint2*)&A[(srow + 32 * i) * P1 + scol] = cvt4h(stA[i]);
#pragma unroll
    for (int i = 0; i < 8; i++)
      *(uint2*)&Bm[(srow + 32 * i) * P1 + scol] = cvt4h(stB[i]);
    __syncthreads();

    if (c + 1 < NCH) {
      const int kc = (c + 1) * 32;
#pragma unroll
      for (int i = 0; i < 4; i++)
        stA[i] = *(const float4*)(Abase + (size_t)(srow + 32 * i) * ND + kc + scol);
#pragma unroll
      for (int i = 0; i < 8; i++)
        stB[i] = *(const float4*)(Bbase + (size_t)(srow + 32 * i) * ND + kc + scol);
    }

    const uint32_t aH = sb + G1_OFFA + buf * G1_ABUF;
    const uint32_t bH = sb + G1_OFFB + buf * G1_BBUF;
#pragma unroll
    for (int kk = 0; kk < 32; kk += 16) {
      uint32_t bq[4][4];
#pragma unroll
      for (int np = 0; np < 4; np++) {
        const uint32_t off = ((warp_n * 64 + np * 16 + b_row) * P1 + kk + b_col) * 2;
        ldsm4(bq[np], bH + off);
      }
#pragma unroll
      for (int mi = 0; mi < 4; mi++) {
        uint32_t ah[4];
        const uint32_t off = ((warp_m * 64 + mi * 16 + a_row) * P1 + kk + a_col) * 2;
        ldsm4(ah, aH + off);
#pragma unroll
        for (int nt = 0; nt < 8; nt++) {
          mma16816(acc[mi][nt], ah, &bq[nt >> 1][(nt & 1) * 2]);
        }
      }
    }
    __syncthreads();
  }

  // epilogue: leaky relu, write P[s][q], full row sums of squares
  const int gm = lane >> 2, tg = lane & 3;
  float* Pb = P + (size_t)b * NS * NQ;
  float rsum[4][2];
#pragma unroll
  for (int mi = 0; mi < 4; mi++) {
    rsum[mi][0] = 0.0f;
    rsum[mi][1] = 0.0f;
    const int sg = s0 + warp_m * 64 + mi * 16 + gm;
#pragma unroll
    for (int nt = 0; nt < 8; nt++) {
      const int qg = warp_n * 64 + nt * 8 + tg * 2;
      float* c = acc[mi][nt];
      float2 v0 = make_float2(c[0] > 0.f ? c[0] : SLOPE * c[0],
                              c[1] > 0.f ? c[1] : SLOPE * c[1]);
      float2 v1 = make_float2(c[2] > 0.f ? c[2] : SLOPE * c[2],
                              c[3] > 0.f ? c[3] : SLOPE * c[3]);
      *(float2*)(Pb + (size_t)sg * NQ + qg) = v0;
      *(float2*)(Pb + (size_t)(sg + 8) * NQ + qg) = v1;
      rsum[mi][0] += v0.x * v0.x + v0.y * v0.y;
      rsum[mi][1] += v1.x * v1.x + v1.y * v1.y;
    }
  }
#pragma unroll
  for (int mi = 0; mi < 4; mi++) {
#pragma unroll
    for (int h = 0; h < 2; h++) {
      float s = rsum[mi][h];
      s += __shfl_xor_sync(0xffffffffu, s, 1);
      s += __shfl_xor_sync(0xffffffffu, s, 2);
      if (tg == 0) sred[warp_n][warp_m * 64 + mi * 16 + h * 8 + gm] = s;
    }
  }
  __syncthreads();
  if (t < 128) {
    float s = sred[0][t] + sred[1][t] + sred[2][t] + sred[3][t];
    g_invnorm[(size_t)b * NS + s0 + t] = 1.0f / (sqrtf(s) + EPS);
  }
}

// ===========================================================================
// Fused softmax (R15 form, reads g_invnorm directly): QT=32 q-tile, 2 CTAs/SM.
// exp2_fma + register column partials; writes fp32 attnT + fp16 g_ah.
// ===========================================================================
#define QT 32
#define TPAD 36
#define SM_SOFT ((NS * TPAD + NS + QT + 256 * 4) * 4)

__global__ __launch_bounds__(256) void k_softmax(float* __restrict__ P) {
  extern __shared__ float sm[];
  float (*tile)[TPAD] = (float(*)[TPAD])sm;
  float* siv = sm + NS * TPAD;
  float* sden = siv + NS;
  float (*spart)[4] = (float(*)[4])(sden + QT);

  const int b = blockIdx.y, q0 = blockIdx.x * QT;
  const int t = threadIdx.x;

  const float KF = SMOOTH * LOG2E;
  for (int s = t; s < NS; s += 256)
    siv[s] = KF * g_invnorm[(size_t)b * NS + s];
  __syncthreads();

  float* Pb = P + (size_t)b * NS * NQ;
  const int c4 = (t & 7) * 4;
  float4 part = make_float4(0.f, 0.f, 0.f, 0.f);
#pragma unroll
  for (int k = 0; k < 16; k++) {
    const int row = (t >> 3) + 32 * k;
    float4 v = *(const float4*)(Pb + (size_t)row * NQ + q0 + c4);
    const float fr = siv[row];
    v.x = exp2_fma(v.x * fr);
    v.y = exp2_fma(v.y * fr);
    v.z = exp2_fma(v.z * fr);
    v.w = exp2_fma(v.w * fr);
    *(float4*)&tile[row][c4] = v;
    part.x += v.x;
    part.y += v.y;
    part.z += v.z;
    part.w += v.w;
  }
  *(float4*)spart[t] = part;
  __syncthreads();

  if (t < QT) {
    const int gidx = t >> 2, comp = t & 3;
    float s = 0.0f;
#pragma unroll
    for (int k = 0; k < 32; k++) s += spart[gidx + 8 * k][comp];
    sden[t] = 1.0f / s;
  }
  __syncthreads();

  __half* Ab = g_ah + (size_t)b * NS * NQ;
  for (int idx = t; idx < NS * (QT / 4); idx += 256) {
    const int row = idx >> 3, cc = (idx & 7) * 4;
    float4 v = *(const float4*)&tile[row][cc];
    v.x *= sden[cc + 0];
    v.y *= sden[cc + 1];
    v.z *= sden[cc + 2];
    v.w *= sden[cc + 3];
    *(float4*)(Pb + (size_t)row * NQ + q0 + cc) = v;
    *(uint2*)(Ab + (size_t)row * NQ + q0 + cc) = cvt4h(v);
  }
}

// ===========================================================================
// GEMM2: W[q][d] = sum_s attn[s][q]*ctx[s][d], fp16/fp32 acc.
// CTA tile 128(q) x 256(d). 8 warps (2m x 4n), warp tile 64x64. K-chunk 32.
// A = g_ah fp16 (ldsm.trans), B = ctx fp32->cvt (ldsm.trans).
// ===========================================================================
#define P2A 136  // attn smem row stride (half)
#define P2B 264  // ctx smem row stride (half)
#define G2_ABUF (32 * P2A * 2)   // 8704 B
#define G2_BBUF (32 * P2B * 2)   // 16896 B
#define G2_OFFA 0
#define G2_OFFB (2 * G2_ABUF)    // 17408
#define G2_SMEM (G2_OFFB + 2 * G2_BBUF)  // 51200

__global__ __launch_bounds__(256, 1) void k_weighted_mma(
    const float* __restrict__ ctx, float* __restrict__ W) {
  extern __shared__ __align__(16) char smg[];
  const uint32_t sb = smem_u32(smg);
  __half* smA = (__half*)(smg + G2_OFFA);
  __half* smB = (__half*)(smg + G2_OFFB);

  const int t = threadIdx.x, w = t >> 5, lane = t & 31;
  const int b = blockIdx.z, d0 = blockIdx.x * 256, q0 = blockIdx.y * 128;
  const int warp_m = w >> 2, warp_n = w & 3;

  const __half* Ab = g_ah + (size_t)b * NS * NQ;
  const float* Bb = ctx + (size_t)b * NS * ND;

  // ldmatrix.trans lane addressing — verified mapping
  const int g = lane >> 3, r8 = lane & 7;
  const int a_k = (g >> 1) * 8 + r8, a_m = (g & 1) * 8;
  const int b_k = (g & 1) * 8 + r8, b_n = (g >> 1) * 8;

  float acc[4][8][4];
#pragma unroll
  for (int i = 0; i < 4; i++)
#pragma unroll
    for (int j = 0; j < 8; j++)
#pragma unroll
      for (int k = 0; k < 4; k++) acc[i][j][k] = 0.0f;

  // staging: A (32x128 fp16): 2 uint4/thread; B (32x256 fp32): 8 float4/thread
  const int arow = t >> 4, acol8 = (t & 15) * 8;   // A: rows t>>4 + 16i
  const int brow = t >> 6, bcol4 = (t & 63) * 4;   // B: rows t>>6 + 4i
  uint4 stA[2];
  float4 stB[8];
#pragma unroll
  for (int i = 0; i < 2; i++)
    stA[i] = *(const uint4*)(Ab + (size_t)(arow + 16 * i) * NQ + q0 + acol8);
#pragma unroll
  for (int i = 0; i < 8; i++)
    stB[i] = *(const float4*)(Bb + (size_t)(brow + 4 * i) * ND + d0 + bcol4);

  const int NCH = NS / 32;  // 16 chunks
  for (int c = 0; c < NCH; c++) {
    const int buf = c & 1;
    __half* A = smA + buf * (32 * P2A);
    __half* Bm = smB + buf * (32 * P2B);
#pragma unroll
    for (int i = 0; i < 2; i++)
      *(uint4*)&A[(arow + 16 * i) * P2A + acol8] = stA[i];
#pragma unroll
    for (int i = 0; i < 8; i++)
      *(uint2*)&Bm[(brow + 4 * i) * P2B + bcol4] = cvt4h(stB[i]);
    __syncthreads();

    if (c + 1 < NCH) {
      const int sc = (c + 1) * 32;
#pragma unroll
      for (int i = 0; i < 2; i++)
        stA[i] = *(const uint4*)(Ab + (size_t)(sc + arow + 16 * i) * NQ + q0 + acol8);
#pragma unroll
      for (int i = 0; i < 8; i++)
        stB[i] = *(const float4*)(Bb + (size_t)(sc + brow + 4 * i) * ND + d0 + bcol4);
    }

    const uint32_t aH = sb + G2_OFFA + buf * G2_ABUF;
    const uint32_t bH = sb + G2_OFFB + buf * G2_BBUF;
#pragma unroll
    for (int kk = 0; kk < 32; kk += 16) {
      uint32_t bq[4][4];
#pragma unroll
      for (int np = 0; np < 4; np++) {
        const uint32_t off = ((kk + b_k) * P2B + warp_n * 64 + np * 16 + b_n) * 2;
        ldsm4t(bq[np], bH + off);
      }
#pragma unroll
      for (int mi = 0; mi < 4; mi++) {
        uint32_t ah[4];
        const uint32_t off = ((kk + a_k) * P2A + warp_m * 64 + mi * 16 + a_m) * 2;
        ldsm4t(ah, aH + off);
#pragma unroll
        for (int nt = 0; nt < 8; nt++) {
          mma16816(acc[mi][nt], ah, &bq[nt >> 1][(nt & 1) * 2]);
        }
      }
    }
    __syncthreads();
  }

  const int gm = lane >> 2, tg = lane & 3;
  float* Wb = W + (size_t)b * NQ * ND;
#pragma unroll
  for (int mi = 0; mi < 4; mi++) {
    const int qg = q0 + warp_m * 64 + mi * 16 + gm;
#pragma unroll
    for (int nt = 0; nt < 8; nt++) {
      const int dg = d0 + warp_n * 64 + nt * 8 + tg * 2;
      float* c = acc[mi][nt];
      *(float2*)(Wb + (size_t)qg * ND + dg) = make_float2(c[0], c[1]);
      *(float2*)(Wb + (size_t)(qg + 8) * ND + dg) = make_float2(c[2], c[3]);
    }
  }
}

// ---------------------------------------------------------------------------
// d_out = [ weighted (B,Q,D) | attnT (B,S,Q) ]; attnT region doubles as
// scratch for the score matrix through the softmax chain.
// ---------------------------------------------------------------------------
extern "C" void kernel_launch(void* const* d_in, const int* in_sizes, int n_in,
                              void* d_out, int out_size) {
  const float* qry = (const float*)d_in[0];  // (B,Q,D)
  const float* ctx = (const float*)d_in[1];  // (B,S,D)
  float* W = (float*)d_out;                         // (B,Q,D)
  float* P = (float*)d_out + (size_t)NB * NQ * ND;  // (B,S,Q)

  cudaFuncSetAttribute(k_scores_mma, cudaFuncAttributeMaxDynamicSharedMemorySize, G1_SMEM);
  cudaFuncSetAttribute(k_weighted_mma, cudaFuncAttributeMaxDynamicSharedMemorySize, G2_SMEM);
  cudaFuncSetAttribute(k_softmax, cudaFuncAttributeMaxDynamicSharedMemorySize, SM_SOFT);

  {
    dim3 g(NS / 128, 1, NB);  // (4, 1, 256)
    k_scores_mma<<<g, 256, G1_SMEM>>>(qry, ctx, P);
  }
  {
    dim3 g(NQ / QT, NB);  // (8, 256)
    k_softmax<<<g, 256, SM_SOFT>>>(P);
  }
  {
    dim3 g(ND / 256, NQ / 128, NB);  // (4, 2, 256)
    k_weighted_mma<<<g, 256, G2_SMEM>>>(ctx, W);
  }
}

// round 17
// speedup vs baseline: 1.0866x; 1.0013x over previous
#include <cuda_runtime.h>
#include <cuda_fp16.h>
#include <cstdint>

// Dims fixed by setup_inputs: B=256, Q=256, S=512, D=1024
#define NB 256
#define NQ 256
#define NS 512
#define ND 1024
#define EPS 1e-8f
#define SLOPE 0.1f
#define SMOOTH 9.0f
#define LOG2E 1.4426950408889634f

__device__ float g_invnorm[NB * NS];
__device__ __align__(16) __half g_ah[(size_t)NB * NS * NQ];  // fp16 attn (67MB)

// ---------------------------------------------------------------------------
// helpers
// ---------------------------------------------------------------------------
__device__ __forceinline__ void ldsm4(uint32_t* r, uint32_t addr) {
  asm volatile("ldmatrix.sync.aligned.m8n8.x4.shared.b16 {%0,%1,%2,%3}, [%4];"
               : "=r"(r[0]), "=r"(r[1]), "=r"(r[2]), "=r"(r[3]) : "r"(addr));
}
__device__ __forceinline__ void ldsm4t(uint32_t* r, uint32_t addr) {
  asm volatile("ldmatrix.sync.aligned.m8n8.x4.trans.shared.b16 {%0,%1,%2,%3}, [%4];"
               : "=r"(r[0]), "=r"(r[1]), "=r"(r[2]), "=r"(r[3]) : "r"(addr));
}
__device__ __forceinline__ void mma16816(float* c, const uint32_t* a, const uint32_t* b) {
  asm volatile(
      "mma.sync.aligned.m16n8k16.row.col.f32.f16.f16.f32 "
      "{%0,%1,%2,%3}, {%4,%5,%6,%7}, {%8,%9}, {%0,%1,%2,%3};"
      : "+f"(c[0]), "+f"(c[1]), "+f"(c[2]), "+f"(c[3])
      : "r"(a[0]), "r"(a[1]), "r"(a[2]), "r"(a[3]), "r"(b[0]), "r"(b[1]));
}
__device__ __forceinline__ uint32_t smem_u32(const void* p) {
  uint32_t a;
  asm("{ .reg .u64 t; cvta.to.shared.u64 t, %1; cvt.u32.u64 %0, t; }" : "=r"(a) : "l"(p));
  return a;
}
// fp32x4 -> fp16x4 (RN)
__device__ __forceinline__ uint2 cvt4h(float4 v) {
  __half2 h0 = __floats2half2_rn(v.x, v.y);
  __half2 h1 = __floats2half2_rn(v.z, v.w);
  uint2 h;
  h.x = *(uint32_t*)&h0;
  h.y = *(uint32_t*)&h1;
  return h;
}
// FMA-pipe exp2 (|y| <= ~13): rel err ~2.4e-6
__device__ __forceinline__ float exp2_fma(float y) {
  float n = rintf(y);
  float f = y - n;
  float p = 1.33335581e-3f;
  p = fmaf(p, f, 9.61812910e-3f);
  p = fmaf(p, f, 5.55041087e-2f);
  p = fmaf(p, f, 2.40226507e-1f);
  p = fmaf(p, f, 6.93147181e-1f);
  p = fmaf(p, f, 1.0f);
  return __int_as_float(__float_as_int(p) + (((int)n) << 23));
}

// ===========================================================================
// GEMM1: P[s][q] = leakyrelu( sum_d ctx[s][d]*qry[q][d] ), fp16/fp32 acc.
// CTA tile 128(s) x 256(q). 8 warps (2m x 4n), warp tile 64x64. K-chunk 32,
// double-buffered fp16 smem, reg prefetch, ONE sync per chunk (trailing sync
// removed: STS(c+1) hits the opposite buffer; STS(c+2)'s reuse of buf[c] is
// ordered by the top sync at c+1 since mma(c) precedes STS(c+1) per-warp).
// Epilogue: leaky, P store, complete row l2-norm -> g_invnorm.
// ===========================================================================
#define P1 40  // smem row stride (half)
#define G1_ABUF (128 * P1 * 2)   // 10240 B
#define G1_BBUF (256 * P1 * 2)   // 20480 B
#define G1_OFFA 0
#define G1_OFFB (2 * G1_ABUF)    // 20480
#define G1_SMEM (G1_OFFB + 2 * G1_BBUF)  // 61440

__global__ __launch_bounds__(256, 1) void k_scores_mma(
    const float* __restrict__ qry, const float* __restrict__ ctx,
    float* __restrict__ P) {
  extern __shared__ __align__(16) char smg[];
  __shared__ float sred[4][128];
  const uint32_t sb = smem_u32(smg);
  __half* smA = (__half*)(smg + G1_OFFA);
  __half* smB = (__half*)(smg + G1_OFFB);

  const int t = threadIdx.x, w = t >> 5, lane = t & 31;
  const int b = blockIdx.z, s0 = blockIdx.x * 128;
  const int warp_m = w >> 2, warp_n = w & 3;

  const float* Abase = ctx + ((size_t)(b * NS + s0)) * ND;  // 128 s-rows
  const float* Bbase = qry + ((size_t)b * NQ) * ND;         // all 256 q-rows

  // ldmatrix lane addressing (non-trans) — verified mapping
  const int g = lane >> 3, r8 = lane & 7;
  const int a_row = (g & 1) * 8 + r8, a_col = (g >> 1) * 8;
  const int b_row = (g >> 1) * 8 + r8, b_col = (g & 1) * 8;

  float acc[4][8][4];
#pragma unroll
  for (int i = 0; i < 4; i++)
#pragma unroll
    for (int j = 0; j < 8; j++)
#pragma unroll
      for (int k = 0; k < 4; k++) acc[i][j][k] = 0.0f;

  const int srow = t >> 3, scol = (t & 7) * 4;
  float4 stA[4], stB[8];
#pragma unroll
  for (int i = 0; i < 4; i++)
    stA[i] = *(const float4*)(Abase + (size_t)(srow + 32 * i) * ND + scol);
#pragma unroll
  for (int i = 0; i < 8; i++)
    stB[i] = *(const float4*)(Bbase + (size_t)(srow + 32 * i) * ND + scol);

  const int NCH = ND / 32;  // 32 chunks
  for (int c = 0; c < NCH; c++) {
    const int buf = c & 1;
    __half* A = smA + buf * (128 * P1);
    __half* Bm = smB + buf * (256 * P1);
#pragma unroll
    for (int i = 0; i < 4; i++)
      *(uint2*)&A[(srow + 32 * i) * P1 + scol] = cvt4h(stA[i]);
#pragma unroll
    for (int i = 0; i < 8; i++)
      *(uint2*)&Bm[(srow + 32 * i) * P1 + scol] = cvt4h(stB[i]);
    __syncthreads();  // the ONLY sync per chunk

    if (c + 1 < NCH) {
      const int kc = (c + 1) * 32;
#pragma unroll
      for (int i = 0; i < 4; i++)
        stA[i] = *(const float4*)(Abase + (size_t)(srow + 32 * i) * ND + kc + scol);
#pragma unroll
      for (int i = 0; i < 8; i++)
        stB[i] = *(const float4*)(Bbase + (size_t)(srow + 32 * i) * ND + kc + scol);
    }

    const uint32_t aH = sb + G1_OFFA + buf * G1_ABUF;
    const uint32_t bH = sb + G1_OFFB + buf * G1_BBUF;
#pragma unroll
    for (int kk = 0; kk < 32; kk += 16) {
      uint32_t bq[4][4];
#pragma unroll
      for (int np = 0; np < 4; np++) {
        const uint32_t off = ((warp_n * 64 + np * 16 + b_row) * P1 + kk + b_col) * 2;
        ldsm4(bq[np], bH + off);
      }
#pragma unroll
      for (int mi = 0; mi < 4; mi++) {
        uint32_t ah[4];
        const uint32_t off = ((warp_m * 64 + mi * 16 + a_row) * P1 + kk + a_col) * 2;
        ldsm4(ah, aH + off);
#pragma unroll
        for (int nt = 0; nt < 8; nt++) {
          mma16816(acc[mi][nt], ah, &bq[nt >> 1][(nt & 1) * 2]);
        }
      }
    }
    // no trailing sync (see header comment)
  }

  // epilogue: leaky relu, write P[s][q], full row sums of squares
  const int gm = lane >> 2, tg = lane & 3;
  float* Pb = P + (size_t)b * NS * NQ;
  float rsum[4][2];
#pragma unroll
  for (int mi = 0; mi < 4; mi++) {
    rsum[mi][0] = 0.0f;
    rsum[mi][1] = 0.0f;
    const int sg = s0 + warp_m * 64 + mi * 16 + gm;
#pragma unroll
    for (int nt = 0; nt < 8; nt++) {
      const int qg = warp_n * 64 + nt * 8 + tg * 2;
      float* c = acc[mi][nt];
      float2 v0 = make_float2(c[0] > 0.f ? c[0] : SLOPE * c[0],
                              c[1] > 0.f ? c[1] : SLOPE * c[1]);
      float2 v1 = make_float2(c[2] > 0.f ? c[2] : SLOPE * c[2],
                              c[3] > 0.f ? c[3] : SLOPE * c[3]);
      *(float2*)(Pb + (size_t)sg * NQ + qg) = v0;
      *(float2*)(Pb + (size_t)(sg + 8) * NQ + qg) = v1;
      rsum[mi][0] += v0.x * v0.x + v0.y * v0.y;
      rsum[mi][1] += v1.x * v1.x + v1.y * v1.y;
    }
  }
#pragma unroll
  for (int mi = 0; mi < 4; mi++) {
#pragma unroll
    for (int h = 0; h < 2; h++) {
      float s = rsum[mi][h];
      s += __shfl_xor_sync(0xffffffffu, s, 1);
      s += __shfl_xor_sync(0xffffffffu, s, 2);
      if (tg == 0) sred[warp_n][warp_m * 64 + mi * 16 + h * 8 + gm] = s;
    }
  }
  __syncthreads();
  if (t < 128) {
    float s = sred[0][t] + sred[1][t] + sred[2][t] + sred[3][t];
    g_invnorm[(size_t)b * NS + s0 + t] = 1.0f / (sqrtf(s) + EPS);
  }
}

// ===========================================================================
// Fused softmax (unchanged): QT=32 q-tile, 2 CTAs/SM, exp2_fma,
// register column partials; writes fp32 attnT + fp16 g_ah.
// ===========================================================================
#define QT 32
#define TPAD 36
#define SM_SOFT ((NS * TPAD + NS + QT + 256 * 4) * 4)

__global__ __launch_bounds__(256) void k_softmax(float* __restrict__ P) {
  extern __shared__ float sm[];
  float (*tile)[TPAD] = (float(*)[TPAD])sm;
  float* siv = sm + NS * TPAD;
  float* sden = siv + NS;
  float (*spart)[4] = (float(*)[4])(sden + QT);

  const int b = blockIdx.y, q0 = blockIdx.x * QT;
  const int t = threadIdx.x;

  const float KF = SMOOTH * LOG2E;
  for (int s = t; s < NS; s += 256)
    siv[s] = KF * g_invnorm[(size_t)b * NS + s];
  __syncthreads();

  float* Pb = P + (size_t)b * NS * NQ;
  const int c4 = (t & 7) * 4;
  float4 part = make_float4(0.f, 0.f, 0.f, 0.f);
#pragma unroll
  for (int k = 0; k < 16; k++) {
    const int row = (t >> 3) + 32 * k;
    float4 v = *(const float4*)(Pb + (size_t)row * NQ + q0 + c4);
    const float fr = siv[row];
    v.x = exp2_fma(v.x * fr);
    v.y = exp2_fma(v.y * fr);
    v.z = exp2_fma(v.z * fr);
    v.w = exp2_fma(v.w * fr);
    *(float4*)&tile[row][c4] = v;
    part.x += v.x;
    part.y += v.y;
    part.z += v.z;
    part.w += v.w;
  }
  *(float4*)spart[t] = part;
  __syncthreads();

  if (t < QT) {
    const int gidx = t >> 2, comp = t & 3;
    float s = 0.0f;
#pragma unroll
    for (int k = 0; k < 32; k++) s += spart[gidx + 8 * k][comp];
    sden[t] = 1.0f / s;
  }
  __syncthreads();

  __half* Ab = g_ah + (size_t)b * NS * NQ;
  for (int idx = t; idx < NS * (QT / 4); idx += 256) {
    const int row = idx >> 3, cc = (idx & 7) * 4;
    float4 v = *(const float4*)&tile[row][cc];
    v.x *= sden[cc + 0];
    v.y *= sden[cc + 1];
    v.z *= sden[cc + 2];
    v.w *= sden[cc + 3];
    *(float4*)(Pb + (size_t)row * NQ + q0 + cc) = v;
    *(uint2*)(Ab + (size_t)row * NQ + q0 + cc) = cvt4h(v);
  }
}

// ===========================================================================
// GEMM2: W[q][d] = sum_s attn[s][q]*ctx[s][d], fp16/fp32 acc.
// CTA tile 128(q) x 256(d). 8 warps (2m x 4n), warp tile 64x64. K-chunk 32.
// A = g_ah fp16 (ldsm.trans), B = ctx fp32->cvt (ldsm.trans).
// ONE sync per chunk (same double-buffer argument as GEMM1).
// ===========================================================================
#define P2A 136  // attn smem row stride (half)
#define P2B 264  // ctx smem row stride (half)
#define G2_ABUF (32 * P2A * 2)   // 8704 B
#define G2_BBUF (32 * P2B * 2)   // 16896 B
#define G2_OFFA 0
#define G2_OFFB (2 * G2_ABUF)    // 17408
#define G2_SMEM (G2_OFFB + 2 * G2_BBUF)  // 51200

__global__ __launch_bounds__(256, 1) void k_weighted_mma(
    const float* __restrict__ ctx, float* __restrict__ W) {
  extern __shared__ __align__(16) char smg[];
  const uint32_t sb = smem_u32(smg);
  __half* smA = (__half*)(smg + G2_OFFA);
  __half* smB = (__half*)(smg + G2_OFFB);

  const int t = threadIdx.x, w = t >> 5, lane = t & 31;
  const int b = blockIdx.z, d0 = blockIdx.x * 256, q0 = blockIdx.y * 128;
  const int warp_m = w >> 2, warp_n = w & 3;

  const __half* Ab = g_ah + (size_t)b * NS * NQ;
  const float* Bb = ctx + (size_t)b * NS * ND;

  // ldmatrix.trans lane addressing — verified mapping
  const int g = lane >> 3, r8 = lane & 7;
  const int a_k = (g >> 1) * 8 + r8, a_m = (g & 1) * 8;
  const int b_k = (g & 1) * 8 + r8, b_n = (g >> 1) * 8;

  float acc[4][8][4];
#pragma unroll
  for (int i = 0; i < 4; i++)
#pragma unroll
    for (int j = 0; j < 8; j++)
#pragma unroll
      for (int k = 0; k < 4; k++) acc[i][j][k] = 0.0f;

  const int arow = t >> 4, acol8 = (t & 15) * 8;   // A: rows t>>4 + 16i
  const int brow = t >> 6, bcol4 = (t & 63) * 4;   // B: rows t>>6 + 4i
  uint4 stA[2];
  float4 stB[8];
#pragma unroll
  for (int i = 0; i < 2; i++)
    stA[i] = *(const uint4*)(Ab + (size_t)(arow + 16 * i) * NQ + q0 + acol8);
#pragma unroll
  for (int i = 0; i < 8; i++)
    stB[i] = *(const float4*)(Bb + (size_t)(brow + 4 * i) * ND + d0 + bcol4);

  const int NCH = NS / 32;  // 16 chunks
  for (int c = 0; c < NCH; c++) {
    const int buf = c & 1;
    __half* A = smA + buf * (32 * P2A);
    __half* Bm = smB + buf * (32 * P2B);
#pragma unroll
    for (int i = 0; i < 2; i++)
      *(uint4*)&A[(arow + 16 * i) * P2A + acol8] = stA[i];
#pragma unroll
    for (int i = 0; i < 8; i++)
      *(uint2*)&Bm[(brow + 4 * i) * P2B + bcol4] = cvt4h(stB[i]);
    __syncthreads();  // the ONLY sync per chunk

    if (c + 1 < NCH) {
      const int sc = (c + 1) * 32;
#pragma unroll
      for (int i = 0; i < 2; i++)
        stA[i] = *(const uint4*)(Ab + (size_t)(sc + arow + 16 * i) * NQ + q0 + acol8);
#pragma unroll
      for (int i = 0; i < 8; i++)
        stB[i] = *(const float4*)(Bb + (size_t)(sc + brow + 4 * i) * ND + d0 + bcol4);
    }

    const uint32_t aH = sb + G2_OFFA + buf * G2_ABUF;
    const uint32_t bH = sb + G2_OFFB + buf * G2_BBUF;
#pragma unroll
    for (int kk = 0; kk < 32; kk += 16) {
      uint32_t bq[4][4];
#pragma unroll
      for (int np = 0; np < 4; np++) {
        const uint32_t off = ((kk + b_k) * P2B + warp_n * 64 + np * 16 + b_n) * 2;
        ldsm4t(bq[np], bH + off);
      }
#pragma unroll
      for (int mi = 0; mi < 4; mi++) {
        uint32_t ah[4];
        const uint32_t off = ((kk + a_k) * P2A + warp_m * 64 + mi * 16 + a_m) * 2;
        ldsm4t(ah, aH + off);
#pragma unroll
        for (int nt = 0; nt < 8; nt++) {
          mma16816(acc[mi][nt], ah, &bq[nt >> 1][(nt & 1) * 2]);
        }
      }
    }
    // no trailing sync
  }

  const int gm = lane >> 2, tg = lane & 3;
  float* Wb = W + (size_t)b * NQ * ND;
#pragma unroll
  for (int mi = 0; mi < 4; mi++) {
    const int qg = q0 + warp_m * 64 + mi * 16 + gm;
#pragma unroll
    for (int nt = 0; nt < 8; nt++) {
      const int dg = d0 + warp_n * 64 + nt * 8 + tg * 2;
      float* c = acc[mi][nt];
      *(float2*)(Wb + (size_t)qg * ND + dg) = make_float2(c[0], c[1]);
      *(float2*)(Wb + (size_t)(qg + 8) * ND + dg) = make_float2(c[2], c[3]);
    }
  }
}

// ---------------------------------------------------------------------------
// d_out = [ weighted (B,Q,D) | attnT (B,S,Q) ]; attnT region doubles as
// scratch for the score matrix through the softmax chain.
// ---------------------------------------------------------------------------
extern "C" void kernel_launch(void* const* d_in, const int* in_sizes, int n_in,
                              void* d_out, int out_size) {
  const float* qry = (const float*)d_in[0];  // (B,Q,D)
  const float* ctx = (const float*)d_in[1];  // (B,S,D)
  float* W = (float*)d_out;                         // (B,Q,D)
  float* P = (float*)d_out + (size_t)NB * NQ * ND;  // (B,S,Q)

  cudaFuncSetAttribute(k_scores_mma, cudaFuncAttributeMaxDynamicSharedMemorySize, G1_SMEM);
  cudaFuncSetAttribute(k_weighted_mma, cudaFuncAttributeMaxDynamicSharedMemorySize, G2_SMEM);
  cudaFuncSetAttribute(k_softmax, cudaFuncAttributeMaxDynamicSharedMemorySize, SM_SOFT);

  {
    dim3 g(NS / 128, 1, NB);  // (4, 1, 256)
    k_scores_mma<<<g, 256, G1_SMEM>>>(qry, ctx, P);
  }
  {
    dim3 g(NQ / QT, NB);  // (8, 256)
    k_softmax<<<g, 256, SM_SOFT>>>(P);
  }
  {
    dim3 g(ND / 256, NQ / 128, NB);  // (4, 2, 256)
    k_weighted_mma<<<g, 256, G2_SMEM>>>(ctx, W);
  }
}